// round 13
// baseline (speedup 1.0000x reference)
#include <cuda_runtime.h>
#include <cuda_bf16.h>
#include <math.h>
#include <stdint.h>

#define BL    8000
#define MPAD  8192
#define DM    512
#define DFF   2048
#define NL    4
#define LSEQ  1000
#define NB    8
#define NH    8
#define DKH   64
#define PP    16

// ---------------- scratch (device globals; no allocation allowed) ----------------
__device__ float g_h  [BL * DM];
__device__ float g_t1 [BL * DM];
__device__ float g_t2 [BL * DM];

// bf16 split weight buffers (transposed to [N,K])
__device__ __nv_bfloat16 g_wqh[NL * DM * DM];
__device__ __nv_bfloat16 g_wql[NL * DM * DM];
__device__ __nv_bfloat16 g_wkh[NL * DM * DM];
__device__ __nv_bfloat16 g_wkl[NL * DM * DM];
__device__ __nv_bfloat16 g_wvh[NL * DM * DM];
__device__ __nv_bfloat16 g_wvl[NL * DM * DM];
__device__ __nv_bfloat16 g_woh[NL * DM * DM];
__device__ __nv_bfloat16 g_wol[NL * DM * DM];
__device__ __nv_bfloat16 g_w1h[NL * DM * DFF];
__device__ __nv_bfloat16 g_w1l[NL * DM * DFF];
__device__ __nv_bfloat16 g_w2h[NL * DFF * DM];
__device__ __nv_bfloat16 g_w2l[NL * DFF * DM];
// bf16 split activation buffers
__device__ __nv_bfloat16 g_ah [MPAD * DM];
__device__ __nv_bfloat16 g_al [MPAD * DM];
__device__ __nv_bfloat16 g_ffh[MPAD * DFF];
__device__ __nv_bfloat16 g_ffl[MPAD * DFF];
// split qkv
__device__ __nv_bfloat16 g_qh [MPAD * DM];
__device__ __nv_bfloat16 g_ql [MPAD * DM];
__device__ __nv_bfloat16 g_kh [MPAD * DM];
__device__ __nv_bfloat16 g_kl [MPAD * DM];
__device__ __nv_bfloat16 g_vh [MPAD * DM];
__device__ __nv_bfloat16 g_vl [MPAD * DM];
// learned-mask projections (bf16)
__device__ __nv_bfloat16 g_qp [BL * NH * PP];
__device__ __nv_bfloat16 g_kp [BL * NH * PP];

// ================= PTX helpers (baseline ISA only) =================
__device__ __forceinline__ uint32_t smem_u32(const void* p) {
    uint32_t a;
    asm("{ .reg .u64 t; cvta.to.shared.u64 t, %1; cvt.u32.u64 %0, t; }" : "=r"(a) : "l"(p));
    return a;
}
__device__ __forceinline__ void cpa16(uint32_t s, const void* g) {
    asm volatile("cp.async.cg.shared.global [%0], [%1], 16;" :: "r"(s), "l"(g));
}
__device__ __forceinline__ void cpa16z(uint32_t s, const void* g, int sz) {
    asm volatile("cp.async.cg.shared.global [%0], [%1], 16, %2;" :: "r"(s), "l"(g), "r"(sz));
}
#define CP_COMMIT() asm volatile("cp.async.commit_group;" ::: "memory")
#define CP_WAIT(n)  asm volatile("cp.async.wait_group %0;" :: "n"(n) : "memory")

__device__ __forceinline__ void ldsm4(uint32_t* r, uint32_t addr) {
    asm volatile("ldmatrix.sync.aligned.m8n8.x4.shared.b16 {%0,%1,%2,%3}, [%4];"
                 : "=r"(r[0]), "=r"(r[1]), "=r"(r[2]), "=r"(r[3]) : "r"(addr));
}
__device__ __forceinline__ void ldsm4t(uint32_t* r, uint32_t addr) {
    asm volatile("ldmatrix.sync.aligned.m8n8.x4.trans.shared.b16 {%0,%1,%2,%3}, [%4];"
                 : "=r"(r[0]), "=r"(r[1]), "=r"(r[2]), "=r"(r[3]) : "r"(addr));
}
__device__ __forceinline__ void mma16816(float* d, const uint32_t* a, const uint32_t* b) {
    asm volatile("mma.sync.aligned.m16n8k16.row.col.f32.bf16.bf16.f32 "
                 "{%0,%1,%2,%3}, {%4,%5,%6,%7}, {%8,%9}, {%0,%1,%2,%3};"
                 : "+f"(d[0]), "+f"(d[1]), "+f"(d[2]), "+f"(d[3])
                 : "r"(a[0]), "r"(a[1]), "r"(a[2]), "r"(a[3]), "r"(b[0]), "r"(b[1]));
}
__device__ __forceinline__ float tanh_fast(float x) {
    float r;
    asm("tanh.approx.f32 %0, %1;" : "=f"(r) : "f"(x));
    return r;
}
__device__ __forceinline__ void split_bf16(float v, __nv_bfloat16& hi, __nv_bfloat16& lo) {
    hi = __float2bfloat16(v);
    lo = __float2bfloat16(v - __bfloat162float(hi));
}
__device__ __forceinline__ uint32_t pack_hi(float a, float b) {
    __nv_bfloat162 h; h.x = __float2bfloat16(a); h.y = __float2bfloat16(b);
    return *(uint32_t*)&h;
}
__device__ __forceinline__ uint32_t pack_lo(float a, float b) {
    __nv_bfloat16 ha = __float2bfloat16(a), hb = __float2bfloat16(b);
    __nv_bfloat162 h;
    h.x = __float2bfloat16(a - __bfloat162float(ha));
    h.y = __float2bfloat16(b - __bfloat162float(hb));
    return *(uint32_t*)&h;
}

// ---------------- all-weights transpose + split (single launch) ----------------
__global__ __launch_bounds__(256)
void wsplit_all(const float* __restrict__ Wq, const float* __restrict__ Wk,
                const float* __restrict__ Wv, const float* __restrict__ Wo,
                const float* __restrict__ W1, const float* __restrict__ W2,
                __nv_bfloat16* qh, __nv_bfloat16* ql, __nv_bfloat16* kh, __nv_bfloat16* kl,
                __nv_bfloat16* vh, __nv_bfloat16* vl, __nv_bfloat16* oh_, __nv_bfloat16* ol_,
                __nv_bfloat16* f1h, __nv_bfloat16* f1l, __nv_bfloat16* f2h, __nv_bfloat16* f2l)
{
    int t = blockIdx.x;
    int layer = t / 3072, r = t % 3072;
    const float* in; __nv_bfloat16 *oh, *ol;
    int K, N, nx, ky;
    if (r < 1024) {
        int type = r >> 8, tt = r & 255;
        nx = tt & 15; ky = tt >> 4; K = DM; N = DM;
        long off = (long)layer * DM * DM;
        if (type == 0)      { in = Wq + off; oh = qh + off;  ol = ql + off;  }
        else if (type == 1) { in = Wk + off; oh = kh + off;  ol = kl + off;  }
        else if (type == 2) { in = Wv + off; oh = vh + off;  ol = vl + off;  }
        else                { in = Wo + off; oh = oh_ + off; ol = ol_ + off; }
    } else if (r < 2048) {
        int tt = r - 1024;
        nx = tt & 63; ky = tt >> 6; K = DM; N = DFF;
        long off = (long)layer * DM * DFF;
        in = W1 + off; oh = f1h + off; ol = f1l + off;
    } else {
        int tt = r - 2048;
        nx = tt & 15; ky = tt >> 4; K = DFF; N = DM;
        long off = (long)layer * DFF * DM;
        in = W2 + off; oh = f2h + off; ol = f2l + off;
    }

    __shared__ float s[32][33];
    int n0 = nx * 32, k0 = ky * 32;
    int tx = threadIdx.x & 31, ty = threadIdx.x >> 5;
#pragma unroll
    for (int rr = 0; rr < 32; rr += 8)
        s[rr + ty][tx] = in[(size_t)(k0 + rr + ty) * N + n0 + tx];
    __syncthreads();
#pragma unroll
    for (int rr = 0; rr < 32; rr += 8) {
        float v = s[tx][rr + ty];
        __nv_bfloat16 hi, lo; split_bf16(v, hi, lo);
        size_t o = (size_t)(n0 + rr + ty) * K + k0 + tx;
        oh[o] = hi; ol[o] = lo;
    }
}

// ---------------- HMMA bf16-split GEMM: 256x128 CTA tile, 64x64 warp tile ----------------
// Stage: A[256 rows x 128B swz] + B[128 rows x 128B swz] (chunks 0-3 hi, 4-7 lo).
// mode bits: 1=relu, 2=write fp32 C, 4=write split Ch/Cl.
#define GST_A     32768
#define GSTAGE    49152
#define MMA_SMEM  (3 * GSTAGE)

__global__ __launch_bounds__(256, 1)
void mma_gemm(const __nv_bfloat16* __restrict__ Ah, const __nv_bfloat16* __restrict__ Al,
              const __nv_bfloat16* __restrict__ Bh, const __nv_bfloat16* __restrict__ Bl,
              const float* __restrict__ bias, float* __restrict__ C,
              __nv_bfloat16* __restrict__ Ch, __nv_bfloat16* __restrict__ Cl,
              int N, int K, int mode)
{
    extern __shared__ char smraw[];
    uint32_t sb = smem_u32(smraw);

    int tid = threadIdx.x;
    int l = tid & 31, w = tid >> 5;
    int wm = w >> 1, wn = w & 1;            // 4 x 2 warp grid
    int bn = blockIdx.x << 7, bm = blockIdx.y << 8;
    size_t rowb = (size_t)K * 2;

    const char* gAh = (const char*)Ah + (size_t)bm * rowb;
    const char* gAl = (const char*)Al + (size_t)bm * rowb;
    const char* gBh = (const char*)Bh + (size_t)bn * rowb;
    const char* gBl = (const char*)Bl + (size_t)bn * rowb;

    float d[4][8][4];
#pragma unroll
    for (int i = 0; i < 4; i++)
#pragma unroll
        for (int j = 0; j < 8; j++)
#pragma unroll
            for (int t = 0; t < 4; t++) d[i][j][t] = 0.f;

    const int S = K >> 5;

    // 3072 16B-chunks per stage (A 2048 + B 1024); 12 per thread.
#define G_LOAD_STAGE(stg, buf) do { \
    _Pragma("unroll") \
    for (int i = 0; i < 12; i++) { \
        int id = i * 256 + tid; \
        int ab = (id >= 2048); \
        int rem = ab ? (id - 2048) : id; \
        int row = rem >> 3, c = rem & 7; \
        const char* gh = ab ? gBh : gAh; \
        const char* gl = ab ? gBl : gAl; \
        const char* src = (c < 4 ? gh : gl) + (size_t)row * rowb + (size_t)(stg) * 64 + (c & 3) * 16; \
        uint32_t dst = sb + (buf) * GSTAGE + ab * GST_A + row * 128 + ((c ^ (row & 7)) << 4); \
        cpa16(dst, src); \
    } \
} while (0)

    G_LOAD_STAGE(0, 0);
    CP_COMMIT();
    if (S > 1) { G_LOAD_STAGE(1, 1); }
    CP_COMMIT();

    int p = 0;
    for (int s = 0; s < S; s++) {
        if (s + 1 < S) CP_WAIT(1); else CP_WAIT(0);
        __syncthreads();

        if (s + 2 < S) {
            int nb = p + 2; if (nb >= 3) nb -= 3;
            G_LOAD_STAGE(s + 2, nb);
        }
        CP_COMMIT();

        uint32_t bufo = sb + p * GSTAGE;
#pragma unroll
        for (int kk = 0; kk < 2; kk++) {
            uint32_t ahf[4][4], alf[4][4];
#pragma unroll
            for (int mt = 0; mt < 4; mt++) {
                int ra = wm * 64 + mt * 16 + (l & 15);
                int ca = kk * 2 + ((l >> 4) & 1);
                ldsm4(ahf[mt], bufo + ra * 128 + ((ca ^ (ra & 7)) << 4));
                ldsm4(alf[mt], bufo + ra * 128 + (((ca + 4) ^ (ra & 7)) << 4));
            }
            // double-buffered B fragments across the 4 n-groups
            uint32_t bh[2][4], blo[2][4];
            {
                int rb = wn * 64 + (l & 7) + ((l >> 4) & 1) * 8;
                int cb = kk * 2 + ((l >> 3) & 1);
                ldsm4(bh[0],  bufo + GST_A + rb * 128 + ((cb ^ (rb & 7)) << 4));
                ldsm4(blo[0], bufo + GST_A + rb * 128 + (((cb + 4) ^ (rb & 7)) << 4));
            }
#pragma unroll
            for (int g = 0; g < 4; g++) {
                int cur = g & 1, nxt = cur ^ 1;
                if (g < 3) {
                    int rb = wn * 64 + (g + 1) * 16 + (l & 7) + ((l >> 4) & 1) * 8;
                    int cb = kk * 2 + ((l >> 3) & 1);
                    ldsm4(bh[nxt],  bufo + GST_A + rb * 128 + ((cb ^ (rb & 7)) << 4));
                    ldsm4(blo[nxt], bufo + GST_A + rb * 128 + (((cb + 4) ^ (rb & 7)) << 4));
                }
#pragma unroll
                for (int mt = 0; mt < 4; mt++) {
                    mma16816(d[mt][g * 2 + 0], ahf[mt], bh[cur]);
                    mma16816(d[mt][g * 2 + 1], ahf[mt], bh[cur] + 2);
                    mma16816(d[mt][g * 2 + 0], alf[mt], bh[cur]);
                    mma16816(d[mt][g * 2 + 1], alf[mt], bh[cur] + 2);
                    mma16816(d[mt][g * 2 + 0], ahf[mt], blo[cur]);
                    mma16816(d[mt][g * 2 + 1], ahf[mt], blo[cur] + 2);
                }
            }
        }
        if (++p == 3) p = 0;
    }

    // ---- epilogue ----
    bool dorelu = (mode & 1), dof32 = (mode & 2), dosplit = (mode & 4);
#pragma unroll
    for (int mt = 0; mt < 4; mt++) {
        int r0 = bm + wm * 64 + mt * 16 + (l >> 2);
        int r1 = r0 + 8;
#pragma unroll
        for (int nt = 0; nt < 8; nt++) {
            int c = bn + wn * 64 + nt * 8 + (l & 3) * 2;
            float b0 = bias[c], b1 = bias[c + 1];
            float v0 = d[mt][nt][0] + b0, v1 = d[mt][nt][1] + b1;
            float v2 = d[mt][nt][2] + b0, v3 = d[mt][nt][3] + b1;
            if (dorelu) {
                v0 = fmaxf(v0, 0.f); v1 = fmaxf(v1, 0.f);
                v2 = fmaxf(v2, 0.f); v3 = fmaxf(v3, 0.f);
            }
            if (dof32) {
                if (r0 < BL) { float2 t = {v0, v1}; *(float2*)&C[(size_t)r0 * N + c] = t; }
                if (r1 < BL) { float2 t = {v2, v3}; *(float2*)&C[(size_t)r1 * N + c] = t; }
            }
            if (dosplit) {
                if (r0 < BL) {
                    *(uint32_t*)&Ch[(size_t)r0 * N + c] = pack_hi(v0, v1);
                    *(uint32_t*)&Cl[(size_t)r0 * N + c] = pack_lo(v0, v1);
                }
                if (r1 < BL) {
                    *(uint32_t*)&Ch[(size_t)r1 * N + c] = pack_hi(v2, v3);
                    *(uint32_t*)&Cl[(size_t)r1 * N + c] = pack_lo(v2, v3);
                }
            }
        }
    }
}

// ---------------- embed: h = x @ emb_w + emb_b + pe[l], + split out ----------------
__global__ __launch_bounds__(128)
void embed_kernel(const float* __restrict__ x, const float* __restrict__ ew,
                  const float* __restrict__ eb, const float* __restrict__ pe,
                  float* __restrict__ h, __nv_bfloat16* __restrict__ ah,
                  __nv_bfloat16* __restrict__ al)
{
    __shared__ float sx[7];
    int row = blockIdx.x;
    int l   = row % LSEQ;
    int tid = threadIdx.x;
    if (tid < 7) sx[tid] = x[row * 7 + tid];
    __syncthreads();
    for (int d = tid; d < DM; d += 128) {
        float a = eb[d] + pe[l * DM + d];
#pragma unroll
        for (int f = 0; f < 7; f++) a += sx[f] * ew[f * DM + d];
        h[(long)row * DM + d] = a;
        __nv_bfloat16 hi, lo; split_bf16(a, hi, lo);
        ah[(long)row * DM + d] = hi;
        al[(long)row * DM + d] = lo;
    }
}

// ---------------- learned-mask projection (bf16 in / bf16 out) ----------------
__global__ __launch_bounds__(128)
void lmproj_kernel(const __nv_bfloat16* __restrict__ q, const float* __restrict__ w,
                   const float* __restrict__ b, __nv_bfloat16* __restrict__ o)
{
    __shared__ float sw[64 * 16];
    __shared__ float sq[8 * 64];
    int tid = threadIdx.x;
    int r0  = blockIdx.x * 8;
    for (int i = tid; i < 1024; i += 128) sw[i] = w[i];
    for (int i = tid; i < 512;  i += 128) sq[i] = __bfloat162float(q[(long)r0 * 64 + i]);
    __syncthreads();
    int rr = tid >> 4, p = tid & 15;
    float a = b[p];
#pragma unroll
    for (int d = 0; d < 64; d++) a += sq[rr * 64 + d] * sw[d * 16 + p];
    o[(long)(r0 + rr) * 16 + p] = __float2bfloat16(a);
}

// ---------------- tensor-core fused attention ----------------
#define SQ_OFF   0
#define SQP_OFF  16384
#define STG_OFF  19456
#define STG_SZ   35840          // K 16384 + V 16384 + KP 3072
#define ATT_SMEM (19456 + 2 * STG_SZ)   // 91136

#define SWZ(base, row, c) \
    ((base) + (row) * 256 + (((c) < 8) ? (((c) ^ ((row) & 7)) << 4) \
                                       : (128 + ((((c) - 8) ^ ((row) & 7)) << 4))))

__global__ __launch_bounds__(128)
void attn_kernel(const __nv_bfloat16* __restrict__ qh, const __nv_bfloat16* __restrict__ ql,
                 const __nv_bfloat16* __restrict__ kh, const __nv_bfloat16* __restrict__ kl,
                 const __nv_bfloat16* __restrict__ vh, const __nv_bfloat16* __restrict__ vl,
                 const __nv_bfloat16* __restrict__ qp, const __nv_bfloat16* __restrict__ kp,
                 __nv_bfloat16* __restrict__ ch, __nv_bfloat16* __restrict__ cl)
{
    extern __shared__ char smraw[];
    uint32_t sb = smem_u32(smraw);
    int tid = threadIdx.x;
    int l = tid & 31, w = tid >> 5;
    int bid = blockIdx.x;
    int qt = bid & 15;
    int h  = (bid >> 4) & 7;
    int b  = bid >> 7;
    int l0 = qt << 6;

    {
#pragma unroll
        for (int i = 0; i < 8; i++) {
            int id = i * 128 + tid;
            int row = id >> 4, c = id & 15;
            int lq = l0 + row;
            const __nv_bfloat16* base = (c < 8) ? qh : ql;
            const __nv_bfloat16* src = base + ((size_t)(b * LSEQ + (lq < LSEQ ? lq : 0))) * DM + h * DKH + (c & 7) * 8;
            cpa16z(SWZ(sb + SQ_OFF, row, c), src, lq < LSEQ ? 16 : 0);
        }
        int row = tid >> 1, cc = tid & 1;
        int lq = l0 + row;
        const __nv_bfloat16* src = qp + ((size_t)((b * LSEQ + (lq < LSEQ ? lq : 0)) * NH + h)) * PP + cc * 8;
        cpa16z(sb + SQP_OFF + row * 48 + cc * 16, src, lq < LSEQ ? 16 : 0);
    }

#define A_LOAD_STAGE(st, buf) do { \
    uint32_t so = sb + STG_OFF + (buf) * STG_SZ; \
    _Pragma("unroll") \
    for (int i = 0; i < 8; i++) { \
        int id = i * 128 + tid; \
        int row = id >> 4, c = id & 15; \
        int s = (st) * 64 + row; \
        int ok = (s < LSEQ) ? 16 : 0; \
        size_t go = ((size_t)(b * LSEQ + (s < LSEQ ? s : 0))) * DM + h * DKH + (c & 7) * 8; \
        cpa16z(SWZ(so, row, c),         ((c < 8) ? kh : kl) + go, ok); \
        cpa16z(SWZ(so + 16384, row, c), ((c < 8) ? vh : vl) + go, ok); \
    } \
    { \
        int row = tid >> 1, cc = tid & 1; \
        int s = (st) * 64 + row; \
        const __nv_bfloat16* src = kp + ((size_t)((b * LSEQ + (s < LSEQ ? s : 0)) * NH + h)) * PP + cc * 8; \
        cpa16z(so + 32768 + row * 48 + cc * 16, src, s < LSEQ ? 16 : 0); \
    } \
} while (0)

    A_LOAD_STAGE(0, 0);
    CP_COMMIT();

    float o[8][4];
#pragma unroll
    for (int i = 0; i < 8; i++)
#pragma unroll
        for (int j = 0; j < 4; j++) o[i][j] = 0.f;
    float m0 = -1e30f, m1 = -1e30f, L0 = 0.f, L1 = 0.f;

    uint32_t aqh[4][4], aql[4][4], aqp[4];

    for (int st = 0; st < 16; st++) {
        int p = st & 1;
        if (st + 1 < 16) {
            A_LOAD_STAGE(st + 1, p ^ 1);
            CP_COMMIT();
            CP_WAIT(1);
        } else {
            CP_WAIT(0);
        }
        __syncthreads();

        if (st == 0) {
#pragma unroll
            for (int kt = 0; kt < 4; kt++) {
                int ra = w * 16 + (l & 15);
                int ca = kt * 2 + ((l >> 4) & 1);
                ldsm4(aqh[kt], SWZ(sb + SQ_OFF, ra, ca));
                ldsm4(aql[kt], SWZ(sb + SQ_OFF, ra, ca + 8));
            }
            ldsm4(aqp, sb + SQP_OFF + (w * 16 + (l & 15)) * 48 + ((l >> 4) & 1) * 16);
        }

        uint32_t so = sb + STG_OFF + p * STG_SZ;

        float msk[8][4];
#pragma unroll
        for (int i = 0; i < 8; i++)
#pragma unroll
            for (int j = 0; j < 4; j++) msk[i][j] = 0.f;
#pragma unroll
        for (int g = 0; g < 4; g++) {
            int rk = g * 16 + (l & 7) + ((l >> 4) & 1) * 8;
            uint32_t bkp[4];
            ldsm4(bkp, so + 32768 + rk * 48 + ((l >> 3) & 1) * 16);
            mma16816(msk[g * 2 + 0], aqp, bkp);
            mma16816(msk[g * 2 + 1], aqp, bkp + 2);
        }

        float sc[8][4];
#pragma unroll
        for (int i = 0; i < 8; i++)
#pragma unroll
            for (int j = 0; j < 4; j++) sc[i][j] = 0.f;
#pragma unroll
        for (int kt = 0; kt < 4; kt++) {
#pragma unroll
            for (int g = 0; g < 4; g++) {
                int rk = g * 16 + (l & 7) + ((l >> 4) & 1) * 8;
                int ck = kt * 2 + ((l >> 3) & 1);
                uint32_t bh[4], bl_[4];
                ldsm4(bh,  SWZ(so, rk, ck));
                ldsm4(bl_, SWZ(so, rk, ck + 8));
                mma16816(sc[g * 2 + 0], aqh[kt], bh);
                mma16816(sc[g * 2 + 1], aqh[kt], bh + 2);
                mma16816(sc[g * 2 + 0], aql[kt], bh);
                mma16816(sc[g * 2 + 1], aql[kt], bh + 2);
                mma16816(sc[g * 2 + 0], aqh[kt], bl_);
                mma16816(sc[g * 2 + 1], aqh[kt], bl_ + 2);
            }
        }

        int s0 = st << 6;
#pragma unroll
        for (int nt = 0; nt < 8; nt++) {
#pragma unroll
            for (int j = 0; j < 4; j++) {
                int col = nt * 8 + (l & 3) * 2 + (j & 1);
                float s = sc[nt][j] * 0.125f + tanh_fast(msk[nt][j]);
                sc[nt][j] = (s0 + col < LSEQ) ? s : -1e30f;
            }
        }

        float mx0 = -1e30f, mx1 = -1e30f;
#pragma unroll
        for (int nt = 0; nt < 8; nt++) {
            mx0 = fmaxf(mx0, fmaxf(sc[nt][0], sc[nt][1]));
            mx1 = fmaxf(mx1, fmaxf(sc[nt][2], sc[nt][3]));
        }
        mx0 = fmaxf(mx0, __shfl_xor_sync(0xffffffffu, mx0, 1));
        mx0 = fmaxf(mx0, __shfl_xor_sync(0xffffffffu, mx0, 2));
        mx1 = fmaxf(mx1, __shfl_xor_sync(0xffffffffu, mx1, 1));
        mx1 = fmaxf(mx1, __shfl_xor_sync(0xffffffffu, mx1, 2));
        float m0n = fmaxf(m0, mx0), m1n = fmaxf(m1, mx1);
        float f0 = __expf(m0 - m0n), f1 = __expf(m1 - m1n);
        m0 = m0n; m1 = m1n;
        float sum0 = 0.f, sum1 = 0.f;
#pragma unroll
        for (int nt = 0; nt < 8; nt++) {
            float p0 = __expf(sc[nt][0] - m0n), p1 = __expf(sc[nt][1] - m0n);
            float p2 = __expf(sc[nt][2] - m1n), p3 = __expf(sc[nt][3] - m1n);
            sc[nt][0] = p0; sc[nt][1] = p1; sc[nt][2] = p2; sc[nt][3] = p3;
            sum0 += p0 + p1; sum1 += p2 + p3;
        }
        sum0 += __shfl_xor_sync(0xffffffffu, sum0, 1);
        sum0 += __shfl_xor_sync(0xffffffffu, sum0, 2);
        sum1 += __shfl_xor_sync(0xffffffffu, sum1, 1);
        sum1 += __shfl_xor_sync(0xffffffffu, sum1, 2);
        L0 = L0 * f0 + sum0;
        L1 = L1 * f1 + sum1;
#pragma unroll
        for (int nt = 0; nt < 8; nt++) {
            o[nt][0] *= f0; o[nt][1] *= f0;
            o[nt][2] *= f1; o[nt][3] *= f1;
        }

#pragma unroll
        for (int kt = 0; kt < 4; kt++) {
            uint32_t ph[4], pl[4];
            ph[0] = pack_hi(sc[2 * kt][0],     sc[2 * kt][1]);
            ph[1] = pack_hi(sc[2 * kt][2],     sc[2 * kt][3]);
            ph[2] = pack_hi(sc[2 * kt + 1][0], sc[2 * kt + 1][1]);
            ph[3] = pack_hi(sc[2 * kt + 1][2], sc[2 * kt + 1][3]);
            pl[0] = pack_lo(sc[2 * kt][0],     sc[2 * kt][1]);
            pl[1] = pack_lo(sc[2 * kt][2],     sc[2 * kt][3]);
            pl[2] = pack_lo(sc[2 * kt + 1][0], sc[2 * kt + 1][1]);
            pl[3] = pack_lo(sc[2 * kt + 1][2], sc[2 * kt + 1][3]);
#pragma unroll
            for (int dp = 0; dp < 4; dp++) {
                int rv = kt * 16 + (l & 7) + ((l >> 3) & 1) * 8;
                int cv = dp * 2 + ((l >> 4) & 1);
                uint32_t bvh[4], bvl[4];
                ldsm4t(bvh, SWZ(so + 16384, rv, cv));
                ldsm4t(bvl, SWZ(so + 16384, rv, cv + 8));
                mma16816(o[dp * 2 + 0], ph, bvh);
                mma16816(o[dp * 2 + 1], ph, bvh + 2);
                mma16816(o[dp * 2 + 0], pl, bvh);
                mma16816(o[dp * 2 + 1], pl, bvh + 2);
                mma16816(o[dp * 2 + 0], ph, bvl);
                mma16816(o[dp * 2 + 1], ph, bvl + 2);
            }
        }
        __syncthreads();
    }

    float rs0 = 1.f / L0, rs1 = 1.f / L1;
    int r0 = w * 16 + (l >> 2);
    int lq0 = l0 + r0, lq1 = lq0 + 8;
#pragma unroll
    for (int dt = 0; dt < 8; dt++) {
        int col = h * DKH + dt * 8 + (l & 3) * 2;
        if (lq0 < LSEQ) {
            size_t off = (size_t)(b * LSEQ + lq0) * DM + col;
            float v0 = o[dt][0] * rs0, v1 = o[dt][1] * rs0;
            *(uint32_t*)&ch[off] = pack_hi(v0, v1);
            *(uint32_t*)&cl[off] = pack_lo(v0, v1);
        }
        if (lq1 < LSEQ) {
            size_t off = (size_t)(b * LSEQ + lq1) * DM + col;
            float v2 = o[dt][2] * rs1, v3 = o[dt][3] * rs1;
            *(uint32_t*)&ch[off] = pack_hi(v2, v3);
            *(uint32_t*)&cl[off] = pack_lo(v2, v3);
        }
    }
}

// ---------------- LayerNorm (+ optional split out) ----------------
__global__ __launch_bounds__(128)
void ln_kernel(float* __restrict__ out, const float* __restrict__ a,
               const float* __restrict__ y, const float* __restrict__ g,
               const float* __restrict__ bb,
               __nv_bfloat16* __restrict__ oh, __nv_bfloat16* __restrict__ ol)
{
    int row = blockIdx.x, tid = threadIdx.x;
    float4 v = ((const float4*)(a + (long)row * DM))[tid];
    if (y) {
        float4 vy = ((const float4*)(y + (long)row * DM))[tid];
        v.x += vy.x; v.y += vy.y; v.z += vy.z; v.w += vy.w;
    }
    float s  = v.x + v.y + v.z + v.w;
    float sq = v.x * v.x + v.y * v.y + v.z * v.z + v.w * v.w;
#pragma unroll
    for (int o = 16; o > 0; o >>= 1) {
        s  += __shfl_xor_sync(0xffffffffu, s,  o);
        sq += __shfl_xor_sync(0xffffffffu, sq, o);
    }
    __shared__ float shs[4], shq[4];
    int wid = tid >> 5;
    if ((tid & 31) == 0) { shs[wid] = s; shq[wid] = sq; }
    __syncthreads();
    s  = shs[0] + shs[1] + shs[2] + shs[3];
    sq = shq[0] + shq[1] + shq[2] + shq[3];
    float mean = s * (1.f / DM);
    float var  = sq * (1.f / DM) - mean * mean;
    float rstd = rsqrtf(var + 1e-5f);
    float4 gg = ((const float4*)g)[tid];
    float4 bv = ((const float4*)bb)[tid];
    float4 o4;
    o4.x = (v.x - mean) * rstd * gg.x + bv.x;
    o4.y = (v.y - mean) * rstd * gg.y + bv.y;
    o4.z = (v.z - mean) * rstd * gg.z + bv.z;
    o4.w = (v.w - mean) * rstd * gg.w + bv.w;
    ((float4*)(out + (long)row * DM))[tid] = o4;
    if (oh) {
        ((uint32_t*)(oh + (long)row * DM))[tid * 2]     = pack_hi(o4.x, o4.y);
        ((uint32_t*)(oh + (long)row * DM))[tid * 2 + 1] = pack_hi(o4.z, o4.w);
        ((uint32_t*)(ol + (long)row * DM))[tid * 2]     = pack_lo(o4.x, o4.y);
        ((uint32_t*)(ol + (long)row * DM))[tid * 2 + 1] = pack_lo(o4.z, o4.w);
    }
}

// ---------------- final FC on last token ----------------
__global__ __launch_bounds__(64)
void fc_kernel(const float* __restrict__ hin, const float* __restrict__ w,
               const float* __restrict__ b, float* __restrict__ out)
{
    __shared__ float sh[512];
    int tid = threadIdx.x;
    int bb  = blockIdx.x;
    const float* row = hin + ((long)bb * LSEQ + (LSEQ - 1)) * DM;
    for (int i = tid; i < 512; i += 64) sh[i] = row[i];
    __syncthreads();
    if (tid < 50) {
        float a = b[tid];
#pragma unroll 8
        for (int d = 0; d < 512; d++) a += sh[d] * w[d * 50 + tid];
        out[bb * 50 + tid] = a;
    }
}

// ---------------- launch ----------------
extern "C" void kernel_launch(void* const* d_in, const int* in_sizes, int n_in,
                              void* d_out, int out_size)
{
    const float* x     = (const float*)d_in[0];
    const float* emb_w = (const float*)d_in[1];
    const float* emb_b = (const float*)d_in[2];
    const float* pe    = (const float*)d_in[3];
    const float* Wq    = (const float*)d_in[4];
    const float* bq    = (const float*)d_in[5];
    const float* Wk    = (const float*)d_in[6];
    const float* bk    = (const float*)d_in[7];
    const float* Wv    = (const float*)d_in[8];
    const float* bv    = (const float*)d_in[9];
    const float* Wo    = (const float*)d_in[10];
    const float* bo    = (const float*)d_in[11];
    const float* W1    = (const float*)d_in[12];
    const float* b1    = (const float*)d_in[13];
    const float* W2    = (const float*)d_in[14];
    const float* b2    = (const float*)d_in[15];
    const float* g1    = (const float*)d_in[16];
    const float* be1   = (const float*)d_in[17];
    const float* g2    = (const float*)d_in[18];
    const float* be2   = (const float*)d_in[19];
    const float* lm_qw = (const float*)d_in[20];
    const float* lm_qb = (const float*)d_in[21];
    const float* lm_kw = (const float*)d_in[22];
    const float* lm_kb = (const float*)d_in[23];
    const float* gn    = (const float*)d_in[24];
    const float* bn    = (const float*)d_in[25];
    const float* fc_w  = (const float*)d_in[26];
    const float* fc_b  = (const float*)d_in[27];
    float* out = (float*)d_out;

    float *h, *t1, *t2;
    cudaGetSymbolAddress((void**)&h,  g_h);
    cudaGetSymbolAddress((void**)&t1, g_t1);
    cudaGetSymbolAddress((void**)&t2, g_t2);

    __nv_bfloat16 *wqh, *wql, *wkh, *wkl, *wvh, *wvl, *woh, *wol;
    __nv_bfloat16 *w1h, *w1l, *w2h, *w2l, *ah, *al, *ffh, *ffl;
    __nv_bfloat16 *qh, *ql, *kh, *kl, *vh, *vl, *qpb, *kpb;
    cudaGetSymbolAddress((void**)&wqh, g_wqh);
    cudaGetSymbolAddress((void**)&wql, g_wql);
    cudaGetSymbolAddress((void**)&wkh, g_wkh);
    cudaGetSymbolAddress((void**)&wkl, g_wkl);
    cudaGetSymbolAddress((void**)&wvh, g_wvh);
    cudaGetSymbolAddress((void**)&wvl, g_wvl);
    cudaGetSymbolAddress((void**)&woh, g_woh);
    cudaGetSymbolAddress((void**)&wol, g_wol);
    cudaGetSymbolAddress((void**)&w1h, g_w1h);
    cudaGetSymbolAddress((void**)&w1l, g_w1l);
    cudaGetSymbolAddress((void**)&w2h, g_w2h);
    cudaGetSymbolAddress((void**)&w2l, g_w2l);
    cudaGetSymbolAddress((void**)&ah,  g_ah);
    cudaGetSymbolAddress((void**)&al,  g_al);
    cudaGetSymbolAddress((void**)&ffh, g_ffh);
    cudaGetSymbolAddress((void**)&ffl, g_ffl);
    cudaGetSymbolAddress((void**)&qh,  g_qh);
    cudaGetSymbolAddress((void**)&ql,  g_ql);
    cudaGetSymbolAddress((void**)&kh,  g_kh);
    cudaGetSymbolAddress((void**)&kl,  g_kl);
    cudaGetSymbolAddress((void**)&vh,  g_vh);
    cudaGetSymbolAddress((void**)&vl,  g_vl);
    cudaGetSymbolAddress((void**)&qpb, g_qp);
    cudaGetSymbolAddress((void**)&kpb, g_kp);

    cudaFuncSetAttribute(attn_kernel, cudaFuncAttributeMaxDynamicSharedMemorySize, ATT_SMEM);
    cudaFuncSetAttribute(mma_gemm,    cudaFuncAttributeMaxDynamicSharedMemorySize, MMA_SMEM);

    wsplit_all<<<NL * 3072, 256>>>(Wq, Wk, Wv, Wo, W1, W2,
                                   wqh, wql, wkh, wkl, wvh, wvl, woh, wol,
                                   w1h, w1l, w2h, w2l);
    embed_kernel<<<BL, 128>>>(x, emb_w, emb_b, pe, h, ah, al);

    const int MT = MPAD / 256;     // 32
    dim3 gq(DM / 128, MT);         // (4, 32)
    dim3 gf1(DFF / 128, MT);       // (16, 32)

    for (int i = 0; i < NL; i++) {
        long o512 = (long)i * DM * DM;
        long offf = (long)i * DM * DFF;

        // launch idx (layer 0): 2=Q, 3=K, 4=lmq, 5=V (ncu -s5 -c1 -> V mma_gemm)
        mma_gemm<<<gq, 256, MMA_SMEM>>>(ah, al, wqh + o512, wql + o512, bq + i * DM,
                                        (float*)0, qh, ql, DM, DM, 4);
        mma_gemm<<<gq, 256, MMA_SMEM>>>(ah, al, wkh + o512, wkl + o512, bk + i * DM,
                                        (float*)0, kh, kl, DM, DM, 4);
        lmproj_kernel<<<BL / 8, 128>>>(qh, lm_qw, lm_qb, qpb);
        mma_gemm<<<gq, 256, MMA_SMEM>>>(ah, al, wvh + o512, wvl + o512, bv + i * DM,
                                        (float*)0, vh, vl, DM, DM, 4);
        lmproj_kernel<<<BL / 8, 128>>>(kh, lm_kw, lm_kb, kpb);

        attn_kernel<<<NB * NH * 16, 128, ATT_SMEM>>>(qh, ql, kh, kl, vh, vl, qpb, kpb, ah, al);

        mma_gemm<<<gq, 256, MMA_SMEM>>>(ah, al, woh + o512, wol + o512, bo + i * DM, t1,
                                        (__nv_bfloat16*)0, (__nv_bfloat16*)0, DM, DM, 2);
        ln_kernel<<<BL, 128>>>(h, h, t1, g1 + i * DM, be1 + i * DM, ah, al);

        mma_gemm<<<gf1, 256, MMA_SMEM>>>(ah, al, w1h + offf, w1l + offf, b1 + i * DFF,
                                         (float*)0, ffh, ffl, DFF, DM, 5);
        mma_gemm<<<gq, 256, MMA_SMEM>>>(ffh, ffl, w2h + offf, w2l + offf, b2 + i * DM, t2,
                                        (__nv_bfloat16*)0, (__nv_bfloat16*)0, DM, DFF, 2);

        ln_kernel<<<BL, 128>>>(t1, h, t2, g2 + i * DM, be2 + i * DM,
                               (__nv_bfloat16*)0, (__nv_bfloat16*)0);
        ln_kernel<<<BL, 128>>>(h, t1, t2, g2 + i * DM, be2 + i * DM, ah, al);
    }

    ln_kernel<<<BL, 128>>>(t1, h, (const float*)nullptr, gn, bn,
                           (__nv_bfloat16*)0, (__nv_bfloat16*)0);
    fc_kernel<<<NB, 64>>>(t1, fc_w, fc_b, out);
}

// round 15
// speedup vs baseline: 1.5406x; 1.5406x over previous
#include <cuda_runtime.h>
#include <cuda_bf16.h>
#include <math.h>
#include <stdint.h>

#define BL    8000
#define MPAD  8064
#define DM    512
#define DFF   2048
#define NL    4
#define LSEQ  1000
#define NB    8
#define NH    8
#define DKH   64
#define PP    16

// ---------------- scratch (device globals; no allocation allowed) ----------------
__device__ float g_h  [BL * DM];
__device__ float g_t1 [BL * DM];
__device__ float g_t2 [BL * DM];

// bf16 split weight buffers (transposed to [N,K])
__device__ __nv_bfloat16 g_wqh[NL * DM * DM];
__device__ __nv_bfloat16 g_wql[NL * DM * DM];
__device__ __nv_bfloat16 g_wkh[NL * DM * DM];
__device__ __nv_bfloat16 g_wkl[NL * DM * DM];
__device__ __nv_bfloat16 g_wvh[NL * DM * DM];
__device__ __nv_bfloat16 g_wvl[NL * DM * DM];
__device__ __nv_bfloat16 g_woh[NL * DM * DM];
__device__ __nv_bfloat16 g_wol[NL * DM * DM];
__device__ __nv_bfloat16 g_w1h[NL * DM * DFF];
__device__ __nv_bfloat16 g_w1l[NL * DM * DFF];
__device__ __nv_bfloat16 g_w2h[NL * DFF * DM];
__device__ __nv_bfloat16 g_w2l[NL * DFF * DM];
// bf16 split activation buffers
__device__ __nv_bfloat16 g_ah [MPAD * DM];
__device__ __nv_bfloat16 g_al [MPAD * DM];
__device__ __nv_bfloat16 g_ffh[MPAD * DFF];
__device__ __nv_bfloat16 g_ffl[MPAD * DFF];
// split qkv
__device__ __nv_bfloat16 g_qh [MPAD * DM];
__device__ __nv_bfloat16 g_ql [MPAD * DM];
__device__ __nv_bfloat16 g_kh [MPAD * DM];
__device__ __nv_bfloat16 g_kl [MPAD * DM];
__device__ __nv_bfloat16 g_vh [MPAD * DM];
__device__ __nv_bfloat16 g_vl [MPAD * DM];
// learned-mask projections (bf16)
__device__ __nv_bfloat16 g_qp [BL * NH * PP];
__device__ __nv_bfloat16 g_kp [BL * NH * PP];

// ================= PTX helpers (baseline ISA only) =================
__device__ __forceinline__ uint32_t smem_u32(const void* p) {
    uint32_t a;
    asm("{ .reg .u64 t; cvta.to.shared.u64 t, %1; cvt.u32.u64 %0, t; }" : "=r"(a) : "l"(p));
    return a;
}
__device__ __forceinline__ void cpa16(uint32_t s, const void* g) {
    asm volatile("cp.async.cg.shared.global [%0], [%1], 16;" :: "r"(s), "l"(g));
}
__device__ __forceinline__ void cpa16z(uint32_t s, const void* g, int sz) {
    asm volatile("cp.async.cg.shared.global [%0], [%1], 16, %2;" :: "r"(s), "l"(g), "r"(sz));
}
#define CP_COMMIT() asm volatile("cp.async.commit_group;" ::: "memory")
#define CP_WAIT(n)  asm volatile("cp.async.wait_group %0;" :: "n"(n) : "memory")

__device__ __forceinline__ void ldsm4(uint32_t* r, uint32_t addr) {
    asm volatile("ldmatrix.sync.aligned.m8n8.x4.shared.b16 {%0,%1,%2,%3}, [%4];"
                 : "=r"(r[0]), "=r"(r[1]), "=r"(r[2]), "=r"(r[3]) : "r"(addr));
}
__device__ __forceinline__ void ldsm4t(uint32_t* r, uint32_t addr) {
    asm volatile("ldmatrix.sync.aligned.m8n8.x4.trans.shared.b16 {%0,%1,%2,%3}, [%4];"
                 : "=r"(r[0]), "=r"(r[1]), "=r"(r[2]), "=r"(r[3]) : "r"(addr));
}
__device__ __forceinline__ void mma16816(float* d, const uint32_t* a, const uint32_t* b) {
    asm volatile("mma.sync.aligned.m16n8k16.row.col.f32.bf16.bf16.f32 "
                 "{%0,%1,%2,%3}, {%4,%5,%6,%7}, {%8,%9}, {%0,%1,%2,%3};"
                 : "+f"(d[0]), "+f"(d[1]), "+f"(d[2]), "+f"(d[3])
                 : "r"(a[0]), "r"(a[1]), "r"(a[2]), "r"(a[3]), "r"(b[0]), "r"(b[1]));
}
__device__ __forceinline__ float tanh_fast(float x) {
    float r;
    asm("tanh.approx.f32 %0, %1;" : "=f"(r) : "f"(x));
    return r;
}
__device__ __forceinline__ void split_bf16(float v, __nv_bfloat16& hi, __nv_bfloat16& lo) {
    hi = __float2bfloat16(v);
    lo = __float2bfloat16(v - __bfloat162float(hi));
}
__device__ __forceinline__ uint32_t pack_hi(float a, float b) {
    __nv_bfloat162 h; h.x = __float2bfloat16(a); h.y = __float2bfloat16(b);
    return *(uint32_t*)&h;
}
__device__ __forceinline__ uint32_t pack_lo(float a, float b) {
    __nv_bfloat16 ha = __float2bfloat16(a), hb = __float2bfloat16(b);
    __nv_bfloat162 h;
    h.x = __float2bfloat16(a - __bfloat162float(ha));
    h.y = __float2bfloat16(b - __bfloat162float(hb));
    return *(uint32_t*)&h;
}

// ---------------- all-weights transpose + split (single launch) ----------------
__global__ __launch_bounds__(256)
void wsplit_all(const float* __restrict__ Wq, const float* __restrict__ Wk,
                const float* __restrict__ Wv, const float* __restrict__ Wo,
                const float* __restrict__ W1, const float* __restrict__ W2,
                __nv_bfloat16* qh, __nv_bfloat16* ql, __nv_bfloat16* kh, __nv_bfloat16* kl,
                __nv_bfloat16* vh, __nv_bfloat16* vl, __nv_bfloat16* oh_, __nv_bfloat16* ol_,
                __nv_bfloat16* f1h, __nv_bfloat16* f1l, __nv_bfloat16* f2h, __nv_bfloat16* f2l)
{
    int t = blockIdx.x;
    int layer = t / 3072, r = t % 3072;
    const float* in; __nv_bfloat16 *oh, *ol;
    int K, N, nx, ky;
    if (r < 1024) {
        int type = r >> 8, tt = r & 255;
        nx = tt & 15; ky = tt >> 4; K = DM; N = DM;
        long off = (long)layer * DM * DM;
        if (type == 0)      { in = Wq + off; oh = qh + off;  ol = ql + off;  }
        else if (type == 1) { in = Wk + off; oh = kh + off;  ol = kl + off;  }
        else if (type == 2) { in = Wv + off; oh = vh + off;  ol = vl + off;  }
        else                { in = Wo + off; oh = oh_ + off; ol = ol_ + off; }
    } else if (r < 2048) {
        int tt = r - 1024;
        nx = tt & 63; ky = tt >> 6; K = DM; N = DFF;
        long off = (long)layer * DM * DFF;
        in = W1 + off; oh = f1h + off; ol = f1l + off;
    } else {
        int tt = r - 2048;
        nx = tt & 15; ky = tt >> 4; K = DFF; N = DM;
        long off = (long)layer * DFF * DM;
        in = W2 + off; oh = f2h + off; ol = f2l + off;
    }

    __shared__ float s[32][33];
    int n0 = nx * 32, k0 = ky * 32;
    int tx = threadIdx.x & 31, ty = threadIdx.x >> 5;
#pragma unroll
    for (int rr = 0; rr < 32; rr += 8)
        s[rr + ty][tx] = in[(size_t)(k0 + rr + ty) * N + n0 + tx];
    __syncthreads();
#pragma unroll
    for (int rr = 0; rr < 32; rr += 8) {
        float v = s[tx][rr + ty];
        __nv_bfloat16 hi, lo; split_bf16(v, hi, lo);
        size_t o = (size_t)(n0 + rr + ty) * K + k0 + tx;
        oh[o] = hi; ol[o] = lo;
    }
}

// ---------------- HMMA bf16-split GEMM core (128x128 CTA, 32x64 warp, 3-stage) ----------------
#define GST       16384
#define GSTAGE    32768
#define MMA_SMEM  (3 * GSTAGE)

#define G_LOAD_STAGE(stg, buf) do { \
    _Pragma("unroll") \
    for (int i = 0; i < 8; i++) { \
        int id = i * 256 + tid; \
        int ab = id >> 10, rem = id & 1023; \
        int row = rem >> 3, c = rem & 7; \
        const char* gh = ab ? gBh : gAh; \
        const char* gl = ab ? gBl : gAl; \
        const char* src = (c < 4 ? gh : gl) + (size_t)row * rowb + (size_t)(stg) * 64 + (c & 3) * 16; \
        uint32_t dst = sb + (buf) * GSTAGE + ab * GST + row * 128 + ((c ^ (row & 7)) << 4); \
        cpa16(dst, src); \
    } \
} while (0)

#define GEMM_MAINLOOP() do { \
    G_LOAD_STAGE(0, 0); \
    CP_COMMIT(); \
    if (S > 1) { G_LOAD_STAGE(1, 1); } \
    CP_COMMIT(); \
    int p = 0; \
    for (int s = 0; s < S; s++) { \
        if (s + 1 < S) CP_WAIT(1); else CP_WAIT(0); \
        __syncthreads(); \
        if (s + 2 < S) { \
            int nb = p + 2; if (nb >= 3) nb -= 3; \
            G_LOAD_STAGE(s + 2, nb); \
        } \
        CP_COMMIT(); \
        uint32_t bufo = sb + p * GSTAGE; \
        _Pragma("unroll") \
        for (int kk = 0; kk < 2; kk++) { \
            uint32_t ahf[2][4], alf[2][4]; \
            _Pragma("unroll") \
            for (int mt = 0; mt < 2; mt++) { \
                int ra = wm * 32 + mt * 16 + (l & 15); \
                int ca = kk * 2 + ((l >> 4) & 1); \
                ldsm4(ahf[mt], bufo + ra * 128 + ((ca ^ (ra & 7)) << 4)); \
                ldsm4(alf[mt], bufo + ra * 128 + (((ca + 4) ^ (ra & 7)) << 4)); \
            } \
            uint32_t bh[2][4], blo[2][4]; \
            { \
                int rb = wn * 64 + (l & 7) + ((l >> 4) & 1) * 8; \
                int cb = kk * 2 + ((l >> 3) & 1); \
                ldsm4(bh[0],  bufo + GST + rb * 128 + ((cb ^ (rb & 7)) << 4)); \
                ldsm4(blo[0], bufo + GST + rb * 128 + (((cb + 4) ^ (rb & 7)) << 4)); \
            } \
            _Pragma("unroll") \
            for (int g = 0; g < 4; g++) { \
                int cur = g & 1, nxt = cur ^ 1; \
                if (g < 3) { \
                    int rb = wn * 64 + (g + 1) * 16 + (l & 7) + ((l >> 4) & 1) * 8; \
                    int cb = kk * 2 + ((l >> 3) & 1); \
                    ldsm4(bh[nxt],  bufo + GST + rb * 128 + ((cb ^ (rb & 7)) << 4)); \
                    ldsm4(blo[nxt], bufo + GST + rb * 128 + (((cb + 4) ^ (rb & 7)) << 4)); \
                } \
                _Pragma("unroll") \
                for (int mt = 0; mt < 2; mt++) { \
                    mma16816(d[mt][g * 2 + 0], ahf[mt], bh[cur]); \
                    mma16816(d[mt][g * 2 + 1], ahf[mt], bh[cur] + 2); \
                    mma16816(d[mt][g * 2 + 0], alf[mt], bh[cur]); \
                    mma16816(d[mt][g * 2 + 1], alf[mt], bh[cur] + 2); \
                    mma16816(d[mt][g * 2 + 0], ahf[mt], blo[cur]); \
                    mma16816(d[mt][g * 2 + 1], ahf[mt], blo[cur] + 2); \
                } \
            } \
        } \
        if (++p == 3) p = 0; \
    } \
} while (0)

// generic single-output GEMM. mode bits: 1=relu, 2=fp32 C, 4=split Ch/Cl.
__global__ __launch_bounds__(256, 2)
void mma_gemm(const __nv_bfloat16* __restrict__ Ah, const __nv_bfloat16* __restrict__ Al,
              const __nv_bfloat16* __restrict__ Bh, const __nv_bfloat16* __restrict__ Bl,
              const float* __restrict__ bias, float* __restrict__ C,
              __nv_bfloat16* __restrict__ Ch, __nv_bfloat16* __restrict__ Cl,
              int N, int K, int mode)
{
    extern __shared__ char smraw[];
    uint32_t sb = smem_u32(smraw);
    int tid = threadIdx.x;
    int l = tid & 31, w = tid >> 5;
    int wm = w >> 1, wn = w & 1;
    int bn = blockIdx.x << 7, bm = blockIdx.y << 7;
    size_t rowb = (size_t)K * 2;

    const char* gAh = (const char*)Ah + (size_t)bm * rowb;
    const char* gAl = (const char*)Al + (size_t)bm * rowb;
    const char* gBh = (const char*)Bh + (size_t)bn * rowb;
    const char* gBl = (const char*)Bl + (size_t)bn * rowb;

    float d[2][8][4];
#pragma unroll
    for (int i = 0; i < 2; i++)
#pragma unroll
        for (int j = 0; j < 8; j++)
#pragma unroll
            for (int t = 0; t < 4; t++) d[i][j][t] = 0.f;

    const int S = K >> 5;
    GEMM_MAINLOOP();

    bool dorelu = (mode & 1), dof32 = (mode & 2), dosplit = (mode & 4);
#pragma unroll
    for (int mt = 0; mt < 2; mt++) {
        int r0 = bm + wm * 32 + mt * 16 + (l >> 2);
        int r1 = r0 + 8;
#pragma unroll
        for (int nt = 0; nt < 8; nt++) {
            int c = bn + wn * 64 + nt * 8 + (l & 3) * 2;
            float b0 = bias[c], b1 = bias[c + 1];
            float v0 = d[mt][nt][0] + b0, v1 = d[mt][nt][1] + b1;
            float v2 = d[mt][nt][2] + b0, v3 = d[mt][nt][3] + b1;
            if (dorelu) {
                v0 = fmaxf(v0, 0.f); v1 = fmaxf(v1, 0.f);
                v2 = fmaxf(v2, 0.f); v3 = fmaxf(v3, 0.f);
            }
            if (dof32) {
                if (r0 < BL) { float2 t = {v0, v1}; *(float2*)&C[(size_t)r0 * N + c] = t; }
                if (r1 < BL) { float2 t = {v2, v3}; *(float2*)&C[(size_t)r1 * N + c] = t; }
            }
            if (dosplit) {
                if (r0 < BL) {
                    *(uint32_t*)&Ch[(size_t)r0 * N + c] = pack_hi(v0, v1);
                    *(uint32_t*)&Cl[(size_t)r0 * N + c] = pack_lo(v0, v1);
                }
                if (r1 < BL) {
                    *(uint32_t*)&Ch[(size_t)r1 * N + c] = pack_hi(v2, v3);
                    *(uint32_t*)&Cl[(size_t)r1 * N + c] = pack_lo(v2, v3);
                }
            }
        }
    }
}

// fused Q/K/V projection: blockIdx.z selects weight/bias/output triple; split-bf16 out.
__global__ __launch_bounds__(256, 2)
void qkv_gemm(const __nv_bfloat16* __restrict__ Ah, const __nv_bfloat16* __restrict__ Al,
              const __nv_bfloat16* __restrict__ B0h, const __nv_bfloat16* __restrict__ B0l,
              const __nv_bfloat16* __restrict__ B1h, const __nv_bfloat16* __restrict__ B1l,
              const __nv_bfloat16* __restrict__ B2h, const __nv_bfloat16* __restrict__ B2l,
              const float* __restrict__ bias0, const float* __restrict__ bias1,
              const float* __restrict__ bias2,
              __nv_bfloat16* __restrict__ C0h, __nv_bfloat16* __restrict__ C0l,
              __nv_bfloat16* __restrict__ C1h, __nv_bfloat16* __restrict__ C1l,
              __nv_bfloat16* __restrict__ C2h, __nv_bfloat16* __restrict__ C2l)
{
    extern __shared__ char smraw[];
    uint32_t sb = smem_u32(smraw);
    int tid = threadIdx.x;
    int l = tid & 31, w = tid >> 5;
    int wm = w >> 1, wn = w & 1;
    int bn = blockIdx.x << 7, bm = blockIdx.y << 7;
    int z  = blockIdx.z;
    const int N = DM, K = DM;
    size_t rowb = (size_t)K * 2;

    const __nv_bfloat16* Bh = (z == 0) ? B0h : (z == 1) ? B1h : B2h;
    const __nv_bfloat16* Bl = (z == 0) ? B0l : (z == 1) ? B1l : B2l;
    const float* bias = (z == 0) ? bias0 : (z == 1) ? bias1 : bias2;
    __nv_bfloat16* Ch = (z == 0) ? C0h : (z == 1) ? C1h : C2h;
    __nv_bfloat16* Cl = (z == 0) ? C0l : (z == 1) ? C1l : C2l;

    const char* gAh = (const char*)Ah + (size_t)bm * rowb;
    const char* gAl = (const char*)Al + (size_t)bm * rowb;
    const char* gBh = (const char*)Bh + (size_t)bn * rowb;
    const char* gBl = (const char*)Bl + (size_t)bn * rowb;

    float d[2][8][4];
#pragma unroll
    for (int i = 0; i < 2; i++)
#pragma unroll
        for (int j = 0; j < 8; j++)
#pragma unroll
            for (int t = 0; t < 4; t++) d[i][j][t] = 0.f;

    const int S = K >> 5;
    GEMM_MAINLOOP();

#pragma unroll
    for (int mt = 0; mt < 2; mt++) {
        int r0 = bm + wm * 32 + mt * 16 + (l >> 2);
        int r1 = r0 + 8;
#pragma unroll
        for (int nt = 0; nt < 8; nt++) {
            int c = bn + wn * 64 + nt * 8 + (l & 3) * 2;
            float b0 = bias[c], b1 = bias[c + 1];
            float v0 = d[mt][nt][0] + b0, v1 = d[mt][nt][1] + b1;
            float v2 = d[mt][nt][2] + b0, v3 = d[mt][nt][3] + b1;
            if (r0 < BL) {
                *(uint32_t*)&Ch[(size_t)r0 * N + c] = pack_hi(v0, v1);
                *(uint32_t*)&Cl[(size_t)r0 * N + c] = pack_lo(v0, v1);
            }
            if (r1 < BL) {
                *(uint32_t*)&Ch[(size_t)r1 * N + c] = pack_hi(v2, v3);
                *(uint32_t*)&Cl[(size_t)r1 * N + c] = pack_lo(v2, v3);
            }
        }
    }
}

// ---------------- embed: h = x @ emb_w + emb_b + pe[l], + split out ----------------
__global__ __launch_bounds__(128)
void embed_kernel(const float* __restrict__ x, const float* __restrict__ ew,
                  const float* __restrict__ eb, const float* __restrict__ pe,
                  float* __restrict__ h, __nv_bfloat16* __restrict__ ah,
                  __nv_bfloat16* __restrict__ al)
{
    __shared__ float sx[7];
    int row = blockIdx.x;
    int l   = row % LSEQ;
    int tid = threadIdx.x;
    if (tid < 7) sx[tid] = x[row * 7 + tid];
    __syncthreads();
    for (int d = tid; d < DM; d += 128) {
        float a = eb[d] + pe[l * DM + d];
#pragma unroll
        for (int f = 0; f < 7; f++) a += sx[f] * ew[f * DM + d];
        h[(long)row * DM + d] = a;
        __nv_bfloat16 hi, lo; split_bf16(a, hi, lo);
        ah[(long)row * DM + d] = hi;
        al[(long)row * DM + d] = lo;
    }
}

// ---------------- learned-mask projection (bf16 in / bf16 out) ----------------
// Covers [BL*NH, DKH] rows 8 per block -> grid must be BL (=64000/8).
__global__ __launch_bounds__(128)
void lmproj_kernel(const __nv_bfloat16* __restrict__ q, const float* __restrict__ w,
                   const float* __restrict__ b, __nv_bfloat16* __restrict__ o)
{
    __shared__ float sw[64 * 16];
    __shared__ float sq[8 * 64];
    int tid = threadIdx.x;
    int r0  = blockIdx.x * 8;
    for (int i = tid; i < 1024; i += 128) sw[i] = w[i];
    for (int i = tid; i < 512;  i += 128) sq[i] = __bfloat162float(q[(long)r0 * 64 + i]);
    __syncthreads();
    int rr = tid >> 4, p = tid & 15;
    float a = b[p];
#pragma unroll
    for (int d = 0; d < 64; d++) a += sq[rr * 64 + d] * sw[d * 16 + p];
    o[(long)(r0 + rr) * 16 + p] = __float2bfloat16(a);
}

// ---------------- tensor-core fused attention ----------------
#define SQ_OFF   0
#define SQP_OFF  16384
#define STG_OFF  19456
#define STG_SZ   35840          // K 16384 + V 16384 + KP 3072
#define ATT_SMEM (19456 + 2 * STG_SZ)   // 91136

#define SWZ(base, row, c) \
    ((base) + (row) * 256 + (((c) < 8) ? (((c) ^ ((row) & 7)) << 4) \
                                       : (128 + ((((c) - 8) ^ ((row) & 7)) << 4))))

__global__ __launch_bounds__(128)
void attn_kernel(const __nv_bfloat16* __restrict__ qh, const __nv_bfloat16* __restrict__ ql,
                 const __nv_bfloat16* __restrict__ kh, const __nv_bfloat16* __restrict__ kl,
                 const __nv_bfloat16* __restrict__ vh, const __nv_bfloat16* __restrict__ vl,
                 const __nv_bfloat16* __restrict__ qp, const __nv_bfloat16* __restrict__ kp,
                 __nv_bfloat16* __restrict__ ch, __nv_bfloat16* __restrict__ cl)
{
    extern __shared__ char smraw[];
    uint32_t sb = smem_u32(smraw);
    int tid = threadIdx.x;
    int l = tid & 31, w = tid >> 5;
    int bid = blockIdx.x;
    int qt = bid & 15;
    int h  = (bid >> 4) & 7;
    int b  = bid >> 7;
    int l0 = qt << 6;

    {
#pragma unroll
        for (int i = 0; i < 8; i++) {
            int id = i * 128 + tid;
            int row = id >> 4, c = id & 15;
            int lq = l0 + row;
            const __nv_bfloat16* base = (c < 8) ? qh : ql;
            const __nv_bfloat16* src = base + ((size_t)(b * LSEQ + (lq < LSEQ ? lq : 0))) * DM + h * DKH + (c & 7) * 8;
            cpa16z(SWZ(sb + SQ_OFF, row, c), src, lq < LSEQ ? 16 : 0);
        }
        int row = tid >> 1, cc = tid & 1;
        int lq = l0 + row;
        const __nv_bfloat16* src = qp + ((size_t)((b * LSEQ + (lq < LSEQ ? lq : 0)) * NH + h)) * PP + cc * 8;
        cpa16z(sb + SQP_OFF + row * 48 + cc * 16, src, lq < LSEQ ? 16 : 0);
    }

#define A_LOAD_STAGE(st, buf) do { \
    uint32_t so = sb + STG_OFF + (buf) * STG_SZ; \
    _Pragma("unroll") \
    for (int i = 0; i < 8; i++) { \
        int id = i * 128 + tid; \
        int row = id >> 4, c = id & 15; \
        int s = (st) * 64 + row; \
        int ok = (s < LSEQ) ? 16 : 0; \
        size_t go = ((size_t)(b * LSEQ + (s < LSEQ ? s : 0))) * DM + h * DKH + (c & 7) * 8; \
        cpa16z(SWZ(so, row, c),         ((c < 8) ? kh : kl) + go, ok); \
        cpa16z(SWZ(so + 16384, row, c), ((c < 8) ? vh : vl) + go, ok); \
    } \
    { \
        int row = tid >> 1, cc = tid & 1; \
        int s = (st) * 64 + row; \
        const __nv_bfloat16* src = kp + ((size_t)((b * LSEQ + (s < LSEQ ? s : 0)) * NH + h)) * PP + cc * 8; \
        cpa16z(so + 32768 + row * 48 + cc * 16, src, s < LSEQ ? 16 : 0); \
    } \
} while (0)

    A_LOAD_STAGE(0, 0);
    CP_COMMIT();

    float o[8][4];
#pragma unroll
    for (int i = 0; i < 8; i++)
#pragma unroll
        for (int j = 0; j < 4; j++) o[i][j] = 0.f;
    float m0 = -1e30f, m1 = -1e30f, L0 = 0.f, L1 = 0.f;

    uint32_t aqh[4][4], aql[4][4], aqp[4];

    for (int st = 0; st < 16; st++) {
        int p = st & 1;
        if (st + 1 < 16) {
            A_LOAD_STAGE(st + 1, p ^ 1);
            CP_COMMIT();
            CP_WAIT(1);
        } else {
            CP_WAIT(0);
        }
        __syncthreads();

        if (st == 0) {
#pragma unroll
            for (int kt = 0; kt < 4; kt++) {
                int ra = w * 16 + (l & 15);
                int ca = kt * 2 + ((l >> 4) & 1);
                ldsm4(aqh[kt], SWZ(sb + SQ_OFF, ra, ca));
                ldsm4(aql[kt], SWZ(sb + SQ_OFF, ra, ca + 8));
            }
            ldsm4(aqp, sb + SQP_OFF + (w * 16 + (l & 15)) * 48 + ((l >> 4) & 1) * 16);
        }

        uint32_t so = sb + STG_OFF + p * STG_SZ;

        float msk[8][4];
#pragma unroll
        for (int i = 0; i < 8; i++)
#pragma unroll
            for (int j = 0; j < 4; j++) msk[i][j] = 0.f;
#pragma unroll
        for (int g = 0; g < 4; g++) {
            int rk = g * 16 + (l & 7) + ((l >> 4) & 1) * 8;
            uint32_t bkp[4];
            ldsm4(bkp, so + 32768 + rk * 48 + ((l >> 3) & 1) * 16);
            mma16816(msk[g * 2 + 0], aqp, bkp);
            mma16816(msk[g * 2 + 1], aqp, bkp + 2);
        }

        float sc[8][4];
#pragma unroll
        for (int i = 0; i < 8; i++)
#pragma unroll
            for (int j = 0; j < 4; j++) sc[i][j] = 0.f;
#pragma unroll
        for (int kt = 0; kt < 4; kt++) {
#pragma unroll
            for (int g = 0; g < 4; g++) {
                int rk = g * 16 + (l & 7) + ((l >> 4) & 1) * 8;
                int ck = kt * 2 + ((l >> 3) & 1);
                uint32_t bh[4], bl_[4];
                ldsm4(bh,  SWZ(so, rk, ck));
                ldsm4(bl_, SWZ(so, rk, ck + 8));
                mma16816(sc[g * 2 + 0], aqh[kt], bh);
                mma16816(sc[g * 2 + 1], aqh[kt], bh + 2);
                mma16816(sc[g * 2 + 0], aql[kt], bh);
                mma16816(sc[g * 2 + 1], aql[kt], bh + 2);
                mma16816(sc[g * 2 + 0], aqh[kt], bl_);
                mma16816(sc[g * 2 + 1], aqh[kt], bl_ + 2);
            }
        }

        int s0 = st << 6;
#pragma unroll
        for (int nt = 0; nt < 8; nt++) {
#pragma unroll
            for (int j = 0; j < 4; j++) {
                int col = nt * 8 + (l & 3) * 2 + (j & 1);
                float s = sc[nt][j] * 0.125f + tanh_fast(msk[nt][j]);
                sc[nt][j] = (s0 + col < LSEQ) ? s : -1e30f;
            }
        }

        float mx0 = -1e30f, mx1 = -1e30f;
#pragma unroll
        for (int nt = 0; nt < 8; nt++) {
            mx0 = fmaxf(mx0, fmaxf(sc[nt][0], sc[nt][1]));
            mx1 = fmaxf(mx1, fmaxf(sc[nt][2], sc[nt][3]));
        }
        mx0 = fmaxf(mx0, __shfl_xor_sync(0xffffffffu, mx0, 1));
        mx0 = fmaxf(mx0, __shfl_xor_sync(0xffffffffu, mx0, 2));
        mx1 = fmaxf(mx1, __shfl_xor_sync(0xffffffffu, mx1, 1));
        mx1 = fmaxf(mx1, __shfl_xor_sync(0xffffffffu, mx1, 2));
        float m0n = fmaxf(m0, mx0), m1n = fmaxf(m1, mx1);
        float f0 = __expf(m0 - m0n), f1 = __expf(m1 - m1n);
        m0 = m0n; m1 = m1n;
        float sum0 = 0.f, sum1 = 0.f;
#pragma unroll
        for (int nt = 0; nt < 8; nt++) {
            float p0 = __expf(sc[nt][0] - m0n), p1 = __expf(sc[nt][1] - m0n);
            float p2 = __expf(sc[nt][2] - m1n), p3 = __expf(sc[nt][3] - m1n);
            sc[nt][0] = p0; sc[nt][1] = p1; sc[nt][2] = p2; sc[nt][3] = p3;
            sum0 += p0 + p1; sum1 += p2 + p3;
        }
        sum0 += __shfl_xor_sync(0xffffffffu, sum0, 1);
        sum0 += __shfl_xor_sync(0xffffffffu, sum0, 2);
        sum1 += __shfl_xor_sync(0xffffffffu, sum1, 1);
        sum1 += __shfl_xor_sync(0xffffffffu, sum1, 2);
        L0 = L0 * f0 + sum0;
        L1 = L1 * f1 + sum1;
#pragma unroll
        for (int nt = 0; nt < 8; nt++) {
            o[nt][0] *= f0; o[nt][1] *= f0;
            o[nt][2] *= f1; o[nt][3] *= f1;
        }

#pragma unroll
        for (int kt = 0; kt < 4; kt++) {
            uint32_t ph[4], pl[4];
            ph[0] = pack_hi(sc[2 * kt][0],     sc[2 * kt][1]);
            ph[1] = pack_hi(sc[2 * kt][2],     sc[2 * kt][3]);
            ph[2] = pack_hi(sc[2 * kt + 1][0], sc[2 * kt + 1][1]);
            ph[3] = pack_hi(sc[2 * kt + 1][2], sc[2 * kt + 1][3]);
            pl[0] = pack_lo(sc[2 * kt][0],     sc[2 * kt][1]);
            pl[1] = pack_lo(sc[2 * kt][2],     sc[2 * kt][3]);
            pl[2] = pack_lo(sc[2 * kt + 1][0], sc[2 * kt + 1][1]);
            pl[3] = pack_lo(sc[2 * kt + 1][2], sc[2 * kt + 1][3]);
#pragma unroll
            for (int dp = 0; dp < 4; dp++) {
                int rv = kt * 16 + (l & 7) + ((l >> 3) & 1) * 8;
                int cv = dp * 2 + ((l >> 4) & 1);
                uint32_t bvh[4], bvl[4];
                ldsm4t(bvh, SWZ(so + 16384, rv, cv));
                ldsm4t(bvl, SWZ(so + 16384, rv, cv + 8));
                mma16816(o[dp * 2 + 0], ph, bvh);
                mma16816(o[dp * 2 + 1], ph, bvh + 2);
                mma16816(o[dp * 2 + 0], pl, bvh);
                mma16816(o[dp * 2 + 1], pl, bvh + 2);
                mma16816(o[dp * 2 + 0], ph, bvl);
                mma16816(o[dp * 2 + 1], ph, bvl + 2);
            }
        }
        __syncthreads();
    }

    float rs0 = 1.f / L0, rs1 = 1.f / L1;
    int r0 = w * 16 + (l >> 2);
    int lq0 = l0 + r0, lq1 = lq0 + 8;
#pragma unroll
    for (int dt = 0; dt < 8; dt++) {
        int col = h * DKH + dt * 8 + (l & 3) * 2;
        if (lq0 < LSEQ) {
            size_t off = (size_t)(b * LSEQ + lq0) * DM + col;
            float v0 = o[dt][0] * rs0, v1 = o[dt][1] * rs0;
            *(uint32_t*)&ch[off] = pack_hi(v0, v1);
            *(uint32_t*)&cl[off] = pack_lo(v0, v1);
        }
        if (lq1 < LSEQ) {
            size_t off = (size_t)(b * LSEQ + lq1) * DM + col;
            float v2 = o[dt][2] * rs1, v3 = o[dt][3] * rs1;
            *(uint32_t*)&ch[off] = pack_hi(v2, v3);
            *(uint32_t*)&cl[off] = pack_lo(v2, v3);
        }
    }
}

// ---------------- LayerNorm (+ optional split out) ----------------
__global__ __launch_bounds__(128)
void ln_kernel(float* __restrict__ out, const float* __restrict__ a,
               const float* __restrict__ y, const float* __restrict__ g,
               const float* __restrict__ bb,
               __nv_bfloat16* __restrict__ oh, __nv_bfloat16* __restrict__ ol)
{
    int row = blockIdx.x, tid = threadIdx.x;
    float4 v = ((const float4*)(a + (long)row * DM))[tid];
    if (y) {
        float4 vy = ((const float4*)(y + (long)row * DM))[tid];
        v.x += vy.x; v.y += vy.y; v.z += vy.z; v.w += vy.w;
    }
    float s  = v.x + v.y + v.z + v.w;
    float sq = v.x * v.x + v.y * v.y + v.z * v.z + v.w * v.w;
#pragma unroll
    for (int o = 16; o > 0; o >>= 1) {
        s  += __shfl_xor_sync(0xffffffffu, s,  o);
        sq += __shfl_xor_sync(0xffffffffu, sq, o);
    }
    __shared__ float shs[4], shq[4];
    int wid = tid >> 5;
    if ((tid & 31) == 0) { shs[wid] = s; shq[wid] = sq; }
    __syncthreads();
    s  = shs[0] + shs[1] + shs[2] + shs[3];
    sq = shq[0] + shq[1] + shq[2] + shq[3];
    float mean = s * (1.f / DM);
    float var  = sq * (1.f / DM) - mean * mean;
    float rstd = rsqrtf(var + 1e-5f);
    float4 gg = ((const float4*)g)[tid];
    float4 bv = ((const float4*)bb)[tid];
    float4 o4;
    o4.x = (v.x - mean) * rstd * gg.x + bv.x;
    o4.y = (v.y - mean) * rstd * gg.y + bv.y;
    o4.z = (v.z - mean) * rstd * gg.z + bv.z;
    o4.w = (v.w - mean) * rstd * gg.w + bv.w;
    ((float4*)(out + (long)row * DM))[tid] = o4;
    if (oh) {
        ((uint32_t*)(oh + (long)row * DM))[tid * 2]     = pack_hi(o4.x, o4.y);
        ((uint32_t*)(oh + (long)row * DM))[tid * 2 + 1] = pack_hi(o4.z, o4.w);
        ((uint32_t*)(ol + (long)row * DM))[tid * 2]     = pack_lo(o4.x, o4.y);
        ((uint32_t*)(ol + (long)row * DM))[tid * 2 + 1] = pack_lo(o4.z, o4.w);
    }
}

// ---------------- fused double-norm: h = LN(LN(h+y)+y), split out ----------------
__global__ __launch_bounds__(128)
void ln2x_kernel(float* __restrict__ hout, const float* __restrict__ hin,
                 const float* __restrict__ y, const float* __restrict__ g,
                 const float* __restrict__ bb,
                 __nv_bfloat16* __restrict__ oh, __nv_bfloat16* __restrict__ ol)
{
    int row = blockIdx.x, tid = threadIdx.x;
    int wid = tid >> 5;
    __shared__ float shs[4], shq[4];

    float4 vy = ((const float4*)(y + (long)row * DM))[tid];
    float4 v  = ((const float4*)(hin + (long)row * DM))[tid];
    v.x += vy.x; v.y += vy.y; v.z += vy.z; v.w += vy.w;
    float4 gg = ((const float4*)g)[tid];
    float4 bv = ((const float4*)bb)[tid];

#pragma unroll
    for (int pass = 0; pass < 2; pass++) {
        float s  = v.x + v.y + v.z + v.w;
        float sq = v.x * v.x + v.y * v.y + v.z * v.z + v.w * v.w;
#pragma unroll
        for (int o = 16; o > 0; o >>= 1) {
            s  += __shfl_xor_sync(0xffffffffu, s,  o);
            sq += __shfl_xor_sync(0xffffffffu, sq, o);
        }
        if ((tid & 31) == 0) { shs[wid] = s; shq[wid] = sq; }
        __syncthreads();
        s  = shs[0] + shs[1] + shs[2] + shs[3];
        sq = shq[0] + shq[1] + shq[2] + shq[3];
        __syncthreads();          // shs/shq reused next pass
        float mean = s * (1.f / DM);
        float var  = sq * (1.f / DM) - mean * mean;
        float rstd = rsqrtf(var + 1e-5f);
        v.x = (v.x - mean) * rstd * gg.x + bv.x;
        v.y = (v.y - mean) * rstd * gg.y + bv.y;
        v.z = (v.z - mean) * rstd * gg.z + bv.z;
        v.w = (v.w - mean) * rstd * gg.w + bv.w;
        if (pass == 0) { v.x += vy.x; v.y += vy.y; v.z += vy.z; v.w += vy.w; }
    }

    ((float4*)(hout + (long)row * DM))[tid] = v;
    ((uint32_t*)(oh + (long)row * DM))[tid * 2]     = pack_hi(v.x, v.y);
    ((uint32_t*)(oh + (long)row * DM))[tid * 2 + 1] = pack_hi(v.z, v.w);
    ((uint32_t*)(ol + (long)row * DM))[tid * 2]     = pack_lo(v.x, v.y);
    ((uint32_t*)(ol + (long)row * DM))[tid * 2 + 1] = pack_lo(v.z, v.w);
}

// ---------------- final FC on last token ----------------
__global__ __launch_bounds__(64)
void fc_kernel(const float* __restrict__ hin, const float* __restrict__ w,
               const float* __restrict__ b, float* __restrict__ out)
{
    __shared__ float sh[512];
    int tid = threadIdx.x;
    int bb  = blockIdx.x;
    const float* row = hin + ((long)bb * LSEQ + (LSEQ - 1)) * DM;
    for (int i = tid; i < 512; i += 64) sh[i] = row[i];
    __syncthreads();
    if (tid < 50) {
        float a = b[tid];
#pragma unroll 8
        for (int d = 0; d < 512; d++) a += sh[d] * w[d * 50 + tid];
        out[bb * 50 + tid] = a;
    }
}

// ---------------- launch ----------------
extern "C" void kernel_launch(void* const* d_in, const int* in_sizes, int n_in,
                              void* d_out, int out_size)
{
    const float* x     = (const float*)d_in[0];
    const float* emb_w = (const float*)d_in[1];
    const float* emb_b = (const float*)d_in[2];
    const float* pe    = (const float*)d_in[3];
    const float* Wq    = (const float*)d_in[4];
    const float* bq    = (const float*)d_in[5];
    const float* Wk    = (const float*)d_in[6];
    const float* bk    = (const float*)d_in[7];
    const float* Wv    = (const float*)d_in[8];
    const float* bv    = (const float*)d_in[9];
    const float* Wo    = (const float*)d_in[10];
    const float* bo    = (const float*)d_in[11];
    const float* W1    = (const float*)d_in[12];
    const float* b1    = (const float*)d_in[13];
    const float* W2    = (const float*)d_in[14];
    const float* b2    = (const float*)d_in[15];
    const float* g1    = (const float*)d_in[16];
    const float* be1   = (const float*)d_in[17];
    const float* g2    = (const float*)d_in[18];
    const float* be2   = (const float*)d_in[19];
    const float* lm_qw = (const float*)d_in[20];
    const float* lm_qb = (const float*)d_in[21];
    const float* lm_kw = (const float*)d_in[22];
    const float* lm_kb = (const float*)d_in[23];
    const float* gn    = (const float*)d_in[24];
    const float* bn    = (const float*)d_in[25];
    const float* fc_w  = (const float*)d_in[26];
    const float* fc_b  = (const float*)d_in[27];
    float* out = (float*)d_out;

    float *h, *t1, *t2;
    cudaGetSymbolAddress((void**)&h,  g_h);
    cudaGetSymbolAddress((void**)&t1, g_t1);
    cudaGetSymbolAddress((void**)&t2, g_t2);

    __nv_bfloat16 *wqh, *wql, *wkh, *wkl, *wvh, *wvl, *woh, *wol;
    __nv_bfloat16 *w1h, *w1l, *w2h, *w2l, *ah, *al, *ffh, *ffl;
    __nv_bfloat16 *qh, *ql, *kh, *kl, *vh, *vl, *qpb, *kpb;
    cudaGetSymbolAddress((void**)&wqh, g_wqh);
    cudaGetSymbolAddress((void**)&wql, g_wql);
    cudaGetSymbolAddress((void**)&wkh, g_wkh);
    cudaGetSymbolAddress((void**)&wkl, g_wkl);
    cudaGetSymbolAddress((void**)&wvh, g_wvh);
    cudaGetSymbolAddress((void**)&wvl, g_wvl);
    cudaGetSymbolAddress((void**)&woh, g_woh);
    cudaGetSymbolAddress((void**)&wol, g_wol);
    cudaGetSymbolAddress((void**)&w1h, g_w1h);
    cudaGetSymbolAddress((void**)&w1l, g_w1l);
    cudaGetSymbolAddress((void**)&w2h, g_w2h);
    cudaGetSymbolAddress((void**)&w2l, g_w2l);
    cudaGetSymbolAddress((void**)&ah,  g_ah);
    cudaGetSymbolAddress((void**)&al,  g_al);
    cudaGetSymbolAddress((void**)&ffh, g_ffh);
    cudaGetSymbolAddress((void**)&ffl, g_ffl);
    cudaGetSymbolAddress((void**)&qh,  g_qh);
    cudaGetSymbolAddress((void**)&ql,  g_ql);
    cudaGetSymbolAddress((void**)&kh,  g_kh);
    cudaGetSymbolAddress((void**)&kl,  g_kl);
    cudaGetSymbolAddress((void**)&vh,  g_vh);
    cudaGetSymbolAddress((void**)&vl,  g_vl);
    cudaGetSymbolAddress((void**)&qpb, g_qp);
    cudaGetSymbolAddress((void**)&kpb, g_kp);

    cudaFuncSetAttribute(attn_kernel, cudaFuncAttributeMaxDynamicSharedMemorySize, ATT_SMEM);
    cudaFuncSetAttribute(mma_gemm,    cudaFuncAttributeMaxDynamicSharedMemorySize, MMA_SMEM);
    cudaFuncSetAttribute(qkv_gemm,    cudaFuncAttributeMaxDynamicSharedMemorySize, MMA_SMEM);

    wsplit_all<<<NL * 3072, 256>>>(Wq, Wk, Wv, Wo, W1, W2,
                                   wqh, wql, wkh, wkl, wvh, wvl, woh, wol,
                                   w1h, w1l, w2h, w2l);
    embed_kernel<<<BL, 128>>>(x, emb_w, emb_b, pe, h, ah, al);

    const int MT = MPAD / 128;     // 63
    dim3 gqkv(DM / 128, MT, 3);    // fused Q/K/V
    dim3 gq(DM / 128, MT);
    dim3 gf1(DFF / 128, MT);

    for (int i = 0; i < NL; i++) {
        long o512 = (long)i * DM * DM;
        long offf = (long)i * DM * DFF;

        // launch idx (layer 0): 2=qkv, 3=lmq, 4=lmk, 5=attn (ncu -s5 -c1 -> attention)
        qkv_gemm<<<gqkv, 256, MMA_SMEM>>>(ah, al,
                                          wqh + o512, wql + o512, wkh + o512, wkl + o512,
                                          wvh + o512, wvl + o512,
                                          bq + i * DM, bk + i * DM, bv + i * DM,
                                          qh, ql, kh, kl, vh, vl);
        lmproj_kernel<<<BL, 128>>>(qh, lm_qw, lm_qb, qpb);
        lmproj_kernel<<<BL, 128>>>(kh, lm_kw, lm_kb, kpb);

        attn_kernel<<<NB * NH * 16, 128, ATT_SMEM>>>(qh, ql, kh, kl, vh, vl, qpb, kpb, ah, al);

        mma_gemm<<<gq, 256, MMA_SMEM>>>(ah, al, woh + o512, wol + o512, bo + i * DM, t1,
                                        (__nv_bfloat16*)0, (__nv_bfloat16*)0, DM, DM, 2);
        ln_kernel<<<BL, 128>>>(h, h, t1, g1 + i * DM, be1 + i * DM, ah, al);

        mma_gemm<<<gf1, 256, MMA_SMEM>>>(ah, al, w1h + offf, w1l + offf, b1 + i * DFF,
                                         (float*)0, ffh, ffl, DFF, DM, 5);
        mma_gemm<<<gq, 256, MMA_SMEM>>>(ffh, ffl, w2h + offf, w2l + offf, b2 + i * DM, t2,
                                        (__nv_bfloat16*)0, (__nv_bfloat16*)0, DM, DFF, 2);

        ln2x_kernel<<<BL, 128>>>(h, h, t2, g2 + i * DM, be2 + i * DM, ah, al);
    }

    ln_kernel<<<BL, 128>>>(t1, h, (const float*)nullptr, gn, bn,
                           (__nv_bfloat16*)0, (__nv_bfloat16*)0);
    fc_kernel<<<NB, 64>>>(t1, fc_w, fc_b, out);
}

// round 16
// speedup vs baseline: 1.5681x; 1.0179x over previous
#include <cuda_runtime.h>
#include <cuda_bf16.h>
#include <math.h>
#include <stdint.h>

#define BL    8000
#define MPAD  8064
#define DM    512
#define DFF   2048
#define NL    4
#define LSEQ  1000
#define NB    8
#define NH    8
#define DKH   64
#define PP    16

// ---------------- scratch (device globals; no allocation allowed) ----------------
__device__ float g_h  [BL * DM];
__device__ float g_t1 [BL * DM];
__device__ float g_t2 [BL * DM];

// bf16 split weight buffers (transposed to [N,K])
__device__ __nv_bfloat16 g_wqh[NL * DM * DM];
__device__ __nv_bfloat16 g_wql[NL * DM * DM];
__device__ __nv_bfloat16 g_wkh[NL * DM * DM];
__device__ __nv_bfloat16 g_wkl[NL * DM * DM];
__device__ __nv_bfloat16 g_wvh[NL * DM * DM];
__device__ __nv_bfloat16 g_wvl[NL * DM * DM];
__device__ __nv_bfloat16 g_woh[NL * DM * DM];
__device__ __nv_bfloat16 g_wol[NL * DM * DM];
__device__ __nv_bfloat16 g_w1h[NL * DM * DFF];
__device__ __nv_bfloat16 g_w1l[NL * DM * DFF];
__device__ __nv_bfloat16 g_w2h[NL * DFF * DM];
__device__ __nv_bfloat16 g_w2l[NL * DFF * DM];
// bf16 split activation buffers
__device__ __nv_bfloat16 g_ah [MPAD * DM];
__device__ __nv_bfloat16 g_al [MPAD * DM];
__device__ __nv_bfloat16 g_ffh[MPAD * DFF];
__device__ __nv_bfloat16 g_ffl[MPAD * DFF];
// split qkv
__device__ __nv_bfloat16 g_qh [MPAD * DM];
__device__ __nv_bfloat16 g_ql [MPAD * DM];
__device__ __nv_bfloat16 g_kh [MPAD * DM];
__device__ __nv_bfloat16 g_kl [MPAD * DM];
__device__ __nv_bfloat16 g_vh [MPAD * DM];
__device__ __nv_bfloat16 g_vl [MPAD * DM];
// learned-mask projections (bf16)
__device__ __nv_bfloat16 g_qp [BL * NH * PP];
__device__ __nv_bfloat16 g_kp [BL * NH * PP];

// ================= PTX helpers (baseline ISA only) =================
__device__ __forceinline__ uint32_t smem_u32(const void* p) {
    uint32_t a;
    asm("{ .reg .u64 t; cvta.to.shared.u64 t, %1; cvt.u32.u64 %0, t; }" : "=r"(a) : "l"(p));
    return a;
}
__device__ __forceinline__ void cpa16(uint32_t s, const void* g) {
    asm volatile("cp.async.cg.shared.global [%0], [%1], 16;" :: "r"(s), "l"(g));
}
__device__ __forceinline__ void cpa16z(uint32_t s, const void* g, int sz) {
    asm volatile("cp.async.cg.shared.global [%0], [%1], 16, %2;" :: "r"(s), "l"(g), "r"(sz));
}
#define CP_COMMIT() asm volatile("cp.async.commit_group;" ::: "memory")
#define CP_WAIT(n)  asm volatile("cp.async.wait_group %0;" :: "n"(n) : "memory")

__device__ __forceinline__ void ldsm4(uint32_t* r, uint32_t addr) {
    asm volatile("ldmatrix.sync.aligned.m8n8.x4.shared.b16 {%0,%1,%2,%3}, [%4];"
                 : "=r"(r[0]), "=r"(r[1]), "=r"(r[2]), "=r"(r[3]) : "r"(addr));
}
__device__ __forceinline__ void ldsm4t(uint32_t* r, uint32_t addr) {
    asm volatile("ldmatrix.sync.aligned.m8n8.x4.trans.shared.b16 {%0,%1,%2,%3}, [%4];"
                 : "=r"(r[0]), "=r"(r[1]), "=r"(r[2]), "=r"(r[3]) : "r"(addr));
}
__device__ __forceinline__ void mma16816(float* d, const uint32_t* a, const uint32_t* b) {
    asm volatile("mma.sync.aligned.m16n8k16.row.col.f32.bf16.bf16.f32 "
                 "{%0,%1,%2,%3}, {%4,%5,%6,%7}, {%8,%9}, {%0,%1,%2,%3};"
                 : "+f"(d[0]), "+f"(d[1]), "+f"(d[2]), "+f"(d[3])
                 : "r"(a[0]), "r"(a[1]), "r"(a[2]), "r"(a[3]), "r"(b[0]), "r"(b[1]));
}
__device__ __forceinline__ float tanh_fast(float x) {
    float r;
    asm("tanh.approx.f32 %0, %1;" : "=f"(r) : "f"(x));
    return r;
}
__device__ __forceinline__ void split_bf16(float v, __nv_bfloat16& hi, __nv_bfloat16& lo) {
    hi = __float2bfloat16(v);
    lo = __float2bfloat16(v - __bfloat162float(hi));
}
__device__ __forceinline__ uint32_t pack_hi(float a, float b) {
    __nv_bfloat162 h; h.x = __float2bfloat16(a); h.y = __float2bfloat16(b);
    return *(uint32_t*)&h;
}
__device__ __forceinline__ uint32_t pack_lo(float a, float b) {
    __nv_bfloat16 ha = __float2bfloat16(a), hb = __float2bfloat16(b);
    __nv_bfloat162 h;
    h.x = __float2bfloat16(a - __bfloat162float(ha));
    h.y = __float2bfloat16(b - __bfloat162float(hb));
    return *(uint32_t*)&h;
}

// ---------------- all-weights transpose + split (single launch) ----------------
__global__ __launch_bounds__(256)
void wsplit_all(const float* __restrict__ Wq, const float* __restrict__ Wk,
                const float* __restrict__ Wv, const float* __restrict__ Wo,
                const float* __restrict__ W1, const float* __restrict__ W2,
                __nv_bfloat16* qh, __nv_bfloat16* ql, __nv_bfloat16* kh, __nv_bfloat16* kl,
                __nv_bfloat16* vh, __nv_bfloat16* vl, __nv_bfloat16* oh_, __nv_bfloat16* ol_,
                __nv_bfloat16* f1h, __nv_bfloat16* f1l, __nv_bfloat16* f2h, __nv_bfloat16* f2l)
{
    int t = blockIdx.x;
    int layer = t / 3072, r = t % 3072;
    const float* in; __nv_bfloat16 *oh, *ol;
    int K, N, nx, ky;
    if (r < 1024) {
        int type = r >> 8, tt = r & 255;
        nx = tt & 15; ky = tt >> 4; K = DM; N = DM;
        long off = (long)layer * DM * DM;
        if (type == 0)      { in = Wq + off; oh = qh + off;  ol = ql + off;  }
        else if (type == 1) { in = Wk + off; oh = kh + off;  ol = kl + off;  }
        else if (type == 2) { in = Wv + off; oh = vh + off;  ol = vl + off;  }
        else                { in = Wo + off; oh = oh_ + off; ol = ol_ + off; }
    } else if (r < 2048) {
        int tt = r - 1024;
        nx = tt & 63; ky = tt >> 6; K = DM; N = DFF;
        long off = (long)layer * DM * DFF;
        in = W1 + off; oh = f1h + off; ol = f1l + off;
    } else {
        int tt = r - 2048;
        nx = tt & 15; ky = tt >> 4; K = DFF; N = DM;
        long off = (long)layer * DFF * DM;
        in = W2 + off; oh = f2h + off; ol = f2l + off;
    }

    __shared__ float s[32][33];
    int n0 = nx * 32, k0 = ky * 32;
    int tx = threadIdx.x & 31, ty = threadIdx.x >> 5;
#pragma unroll
    for (int rr = 0; rr < 32; rr += 8)
        s[rr + ty][tx] = in[(size_t)(k0 + rr + ty) * N + n0 + tx];
    __syncthreads();
#pragma unroll
    for (int rr = 0; rr < 32; rr += 8) {
        float v = s[tx][rr + ty];
        __nv_bfloat16 hi, lo; split_bf16(v, hi, lo);
        size_t o = (size_t)(n0 + rr + ty) * K + k0 + tx;
        oh[o] = hi; ol[o] = lo;
    }
}

// ---------------- HMMA bf16-split GEMM core (128x128 CTA, 32x64 warp, 3-stage) ----------------
#define GST       16384
#define GSTAGE    32768
#define MMA_SMEM  (3 * GSTAGE)

#define G_LOAD_STAGE(stg, buf) do { \
    _Pragma("unroll") \
    for (int i = 0; i < 8; i++) { \
        int id = i * 256 + tid; \
        int ab = id >> 10, rem = id & 1023; \
        int row = rem >> 3, c = rem & 7; \
        const char* gh = ab ? gBh : gAh; \
        const char* gl = ab ? gBl : gAl; \
        const char* src = (c < 4 ? gh : gl) + (size_t)row * rowb + (size_t)(stg) * 64 + (c & 3) * 16; \
        uint32_t dst = sb + (buf) * GSTAGE + ab * GST + row * 128 + ((c ^ (row & 7)) << 4); \
        cpa16(dst, src); \
    } \
} while (0)

// product-major mma order: same-accumulator writes separated by 4 independent mmas
#define GEMM_MAINLOOP() do { \
    G_LOAD_STAGE(0, 0); \
    CP_COMMIT(); \
    if (S > 1) { G_LOAD_STAGE(1, 1); } \
    CP_COMMIT(); \
    int p = 0; \
    for (int s = 0; s < S; s++) { \
        if (s + 1 < S) CP_WAIT(1); else CP_WAIT(0); \
        __syncthreads(); \
        if (s + 2 < S) { \
            int nb = p + 2; if (nb >= 3) nb -= 3; \
            G_LOAD_STAGE(s + 2, nb); \
        } \
        CP_COMMIT(); \
        uint32_t bufo = sb + p * GSTAGE; \
        _Pragma("unroll") \
        for (int kk = 0; kk < 2; kk++) { \
            uint32_t ahf[2][4], alf[2][4]; \
            _Pragma("unroll") \
            for (int mt = 0; mt < 2; mt++) { \
                int ra = wm * 32 + mt * 16 + (l & 15); \
                int ca = kk * 2 + ((l >> 4) & 1); \
                ldsm4(ahf[mt], bufo + ra * 128 + ((ca ^ (ra & 7)) << 4)); \
                ldsm4(alf[mt], bufo + ra * 128 + (((ca + 4) ^ (ra & 7)) << 4)); \
            } \
            uint32_t bh[2][4], blo[2][4]; \
            { \
                int rb = wn * 64 + (l & 7) + ((l >> 4) & 1) * 8; \
                int cb = kk * 2 + ((l >> 3) & 1); \
                ldsm4(bh[0],  bufo + GST + rb * 128 + ((cb ^ (rb & 7)) << 4)); \
                ldsm4(blo[0], bufo + GST + rb * 128 + (((cb + 4) ^ (rb & 7)) << 4)); \
            } \
            _Pragma("unroll") \
            for (int g = 0; g < 4; g++) { \
                int cur = g & 1, nxt = cur ^ 1; \
                if (g < 3) { \
                    int rb = wn * 64 + (g + 1) * 16 + (l & 7) + ((l >> 4) & 1) * 8; \
                    int cb = kk * 2 + ((l >> 3) & 1); \
                    ldsm4(bh[nxt],  bufo + GST + rb * 128 + ((cb ^ (rb & 7)) << 4)); \
                    ldsm4(blo[nxt], bufo + GST + rb * 128 + (((cb + 4) ^ (rb & 7)) << 4)); \
                } \
                mma16816(d[0][g * 2 + 0], ahf[0], bh[cur]); \
                mma16816(d[1][g * 2 + 0], ahf[1], bh[cur]); \
                mma16816(d[0][g * 2 + 1], ahf[0], bh[cur] + 2); \
                mma16816(d[1][g * 2 + 1], ahf[1], bh[cur] + 2); \
                mma16816(d[0][g * 2 + 0], alf[0], bh[cur]); \
                mma16816(d[1][g * 2 + 0], alf[1], bh[cur]); \
                mma16816(d[0][g * 2 + 1], alf[0], bh[cur] + 2); \
                mma16816(d[1][g * 2 + 1], alf[1], bh[cur] + 2); \
                mma16816(d[0][g * 2 + 0], ahf[0], blo[cur]); \
                mma16816(d[1][g * 2 + 0], ahf[1], blo[cur]); \
                mma16816(d[0][g * 2 + 1], ahf[0], blo[cur] + 2); \
                mma16816(d[1][g * 2 + 1], ahf[1], blo[cur] + 2); \
            } \
        } \
        if (++p == 3) p = 0; \
    } \
} while (0)

// generic single-output GEMM. mode bits: 1=relu, 2=fp32 C, 4=split Ch/Cl.
__global__ __launch_bounds__(256, 2)
void mma_gemm(const __nv_bfloat16* __restrict__ Ah, const __nv_bfloat16* __restrict__ Al,
              const __nv_bfloat16* __restrict__ Bh, const __nv_bfloat16* __restrict__ Bl,
              const float* __restrict__ bias, float* __restrict__ C,
              __nv_bfloat16* __restrict__ Ch, __nv_bfloat16* __restrict__ Cl,
              int N, int K, int mode)
{
    extern __shared__ char smraw[];
    uint32_t sb = smem_u32(smraw);
    int tid = threadIdx.x;
    int l = tid & 31, w = tid >> 5;
    int wm = w >> 1, wn = w & 1;
    int bn = blockIdx.x << 7, bm = blockIdx.y << 7;
    size_t rowb = (size_t)K * 2;

    const char* gAh = (const char*)Ah + (size_t)bm * rowb;
    const char* gAl = (const char*)Al + (size_t)bm * rowb;
    const char* gBh = (const char*)Bh + (size_t)bn * rowb;
    const char* gBl = (const char*)Bl + (size_t)bn * rowb;

    float d[2][8][4];
#pragma unroll
    for (int i = 0; i < 2; i++)
#pragma unroll
        for (int j = 0; j < 8; j++)
#pragma unroll
            for (int t = 0; t < 4; t++) d[i][j][t] = 0.f;

    const int S = K >> 5;
    GEMM_MAINLOOP();

    bool dorelu = (mode & 1), dof32 = (mode & 2), dosplit = (mode & 4);
#pragma unroll
    for (int mt = 0; mt < 2; mt++) {
        int r0 = bm + wm * 32 + mt * 16 + (l >> 2);
        int r1 = r0 + 8;
#pragma unroll
        for (int nt = 0; nt < 8; nt++) {
            int c = bn + wn * 64 + nt * 8 + (l & 3) * 2;
            float b0 = bias[c], b1 = bias[c + 1];
            float v0 = d[mt][nt][0] + b0, v1 = d[mt][nt][1] + b1;
            float v2 = d[mt][nt][2] + b0, v3 = d[mt][nt][3] + b1;
            if (dorelu) {
                v0 = fmaxf(v0, 0.f); v1 = fmaxf(v1, 0.f);
                v2 = fmaxf(v2, 0.f); v3 = fmaxf(v3, 0.f);
            }
            if (dof32) {
                if (r0 < BL) { float2 t = {v0, v1}; *(float2*)&C[(size_t)r0 * N + c] = t; }
                if (r1 < BL) { float2 t = {v2, v3}; *(float2*)&C[(size_t)r1 * N + c] = t; }
            }
            if (dosplit) {
                if (r0 < BL) {
                    *(uint32_t*)&Ch[(size_t)r0 * N + c] = pack_hi(v0, v1);
                    *(uint32_t*)&Cl[(size_t)r0 * N + c] = pack_lo(v0, v1);
                }
                if (r1 < BL) {
                    *(uint32_t*)&Ch[(size_t)r1 * N + c] = pack_hi(v2, v3);
                    *(uint32_t*)&Cl[(size_t)r1 * N + c] = pack_lo(v2, v3);
                }
            }
        }
    }
}

// fused Q/K/V projection: blockIdx.z selects weight/bias/output triple; split-bf16 out.
__global__ __launch_bounds__(256, 2)
void qkv_gemm(const __nv_bfloat16* __restrict__ Ah, const __nv_bfloat16* __restrict__ Al,
              const __nv_bfloat16* __restrict__ B0h, const __nv_bfloat16* __restrict__ B0l,
              const __nv_bfloat16* __restrict__ B1h, const __nv_bfloat16* __restrict__ B1l,
              const __nv_bfloat16* __restrict__ B2h, const __nv_bfloat16* __restrict__ B2l,
              const float* __restrict__ bias0, const float* __restrict__ bias1,
              const float* __restrict__ bias2,
              __nv_bfloat16* __restrict__ C0h, __nv_bfloat16* __restrict__ C0l,
              __nv_bfloat16* __restrict__ C1h, __nv_bfloat16* __restrict__ C1l,
              __nv_bfloat16* __restrict__ C2h, __nv_bfloat16* __restrict__ C2l)
{
    extern __shared__ char smraw[];
    uint32_t sb = smem_u32(smraw);
    int tid = threadIdx.x;
    int l = tid & 31, w = tid >> 5;
    int wm = w >> 1, wn = w & 1;
    int bn = blockIdx.x << 7, bm = blockIdx.y << 7;
    int z  = blockIdx.z;
    const int N = DM, K = DM;
    size_t rowb = (size_t)K * 2;

    const __nv_bfloat16* Bh = (z == 0) ? B0h : (z == 1) ? B1h : B2h;
    const __nv_bfloat16* Bl = (z == 0) ? B0l : (z == 1) ? B1l : B2l;
    const float* bias = (z == 0) ? bias0 : (z == 1) ? bias1 : bias2;
    __nv_bfloat16* Ch = (z == 0) ? C0h : (z == 1) ? C1h : C2h;
    __nv_bfloat16* Cl = (z == 0) ? C0l : (z == 1) ? C1l : C2l;

    const char* gAh = (const char*)Ah + (size_t)bm * rowb;
    const char* gAl = (const char*)Al + (size_t)bm * rowb;
    const char* gBh = (const char*)Bh + (size_t)bn * rowb;
    const char* gBl = (const char*)Bl + (size_t)bn * rowb;

    float d[2][8][4];
#pragma unroll
    for (int i = 0; i < 2; i++)
#pragma unroll
        for (int j = 0; j < 8; j++)
#pragma unroll
            for (int t = 0; t < 4; t++) d[i][j][t] = 0.f;

    const int S = K >> 5;
    GEMM_MAINLOOP();

#pragma unroll
    for (int mt = 0; mt < 2; mt++) {
        int r0 = bm + wm * 32 + mt * 16 + (l >> 2);
        int r1 = r0 + 8;
#pragma unroll
        for (int nt = 0; nt < 8; nt++) {
            int c = bn + wn * 64 + nt * 8 + (l & 3) * 2;
            float b0 = bias[c], b1 = bias[c + 1];
            float v0 = d[mt][nt][0] + b0, v1 = d[mt][nt][1] + b1;
            float v2 = d[mt][nt][2] + b0, v3 = d[mt][nt][3] + b1;
            if (r0 < BL) {
                *(uint32_t*)&Ch[(size_t)r0 * N + c] = pack_hi(v0, v1);
                *(uint32_t*)&Cl[(size_t)r0 * N + c] = pack_lo(v0, v1);
            }
            if (r1 < BL) {
                *(uint32_t*)&Ch[(size_t)r1 * N + c] = pack_hi(v2, v3);
                *(uint32_t*)&Cl[(size_t)r1 * N + c] = pack_lo(v2, v3);
            }
        }
    }
}

// ---------------- embed: h = x @ emb_w + emb_b + pe[l], + split out ----------------
__global__ __launch_bounds__(128)
void embed_kernel(const float* __restrict__ x, const float* __restrict__ ew,
                  const float* __restrict__ eb, const float* __restrict__ pe,
                  float* __restrict__ h, __nv_bfloat16* __restrict__ ah,
                  __nv_bfloat16* __restrict__ al)
{
    __shared__ float sx[7];
    int row = blockIdx.x;
    int l   = row % LSEQ;
    int tid = threadIdx.x;
    if (tid < 7) sx[tid] = x[row * 7 + tid];
    __syncthreads();
    for (int d = tid; d < DM; d += 128) {
        float a = eb[d] + pe[l * DM + d];
#pragma unroll
        for (int f = 0; f < 7; f++) a += sx[f] * ew[f * DM + d];
        h[(long)row * DM + d] = a;
        __nv_bfloat16 hi, lo; split_bf16(a, hi, lo);
        ah[(long)row * DM + d] = hi;
        al[(long)row * DM + d] = lo;
    }
}

// ---------------- fused learned-mask projection: q and k in one launch ----------------
// blockIdx.y: 0 -> qp from qh, 1 -> kp from kh. 8 rows of [BL*NH, 64] per block.
// w staged transposed [16][68] so per-thread loads are ld.shared.v4.
__global__ __launch_bounds__(128)
void lmproj2_kernel(const __nv_bfloat16* __restrict__ qh, const __nv_bfloat16* __restrict__ kh,
                    const float* __restrict__ qw, const float* __restrict__ qb,
                    const float* __restrict__ kw, const float* __restrict__ kb,
                    __nv_bfloat16* __restrict__ qp, __nv_bfloat16* __restrict__ kp)
{
    __shared__ float swt[16][68];
    __shared__ float sq[8][64];
    int tid = threadIdx.x;
    int sel = blockIdx.y;
    const __nv_bfloat16* src = sel ? kh : qh;
    const float* w = sel ? kw : qw;
    const float* b = sel ? kb : qb;
    __nv_bfloat16* o = sel ? kp : qp;
    int r0 = blockIdx.x * 8;

    for (int i = tid; i < 1024; i += 128) {
        int dd = i >> 4, pp = i & 15;
        swt[pp][dd] = w[i];
    }
    // 8 rows x 64 bf16 = 512 elems; load as bf162 pairs
    for (int i = tid; i < 256; i += 128) {
        int rr = i >> 5, e2 = i & 31;
        __nv_bfloat162 v = ((const __nv_bfloat162*)(src + (size_t)(r0 + rr) * 64))[e2];
        sq[rr][e2 * 2]     = __bfloat162float(v.x);
        sq[rr][e2 * 2 + 1] = __bfloat162float(v.y);
    }
    __syncthreads();

    int rr = tid >> 4, pp = tid & 15;
    float a = b[pp];
#pragma unroll
    for (int d4 = 0; d4 < 16; d4++) {
        float4 qv = *(const float4*)&sq[rr][d4 * 4];
        float4 wv = *(const float4*)&swt[pp][d4 * 4];
        a += qv.x * wv.x + qv.y * wv.y + qv.z * wv.z + qv.w * wv.w;
    }
    o[(size_t)(r0 + rr) * 16 + pp] = __float2bfloat16(a);
}

// ---------------- tensor-core fused attention ----------------
#define SQ_OFF   0
#define SQP_OFF  16384
#define STG_OFF  19456
#define STG_SZ   35840          // K 16384 + V 16384 + KP 3072
#define ATT_SMEM (19456 + 2 * STG_SZ)   // 91136

#define SWZ(base, row, c) \
    ((base) + (row) * 256 + (((c) < 8) ? (((c) ^ ((row) & 7)) << 4) \
                                       : (128 + ((((c) - 8) ^ ((row) & 7)) << 4))))

__global__ __launch_bounds__(128)
void attn_kernel(const __nv_bfloat16* __restrict__ qh, const __nv_bfloat16* __restrict__ ql,
                 const __nv_bfloat16* __restrict__ kh, const __nv_bfloat16* __restrict__ kl,
                 const __nv_bfloat16* __restrict__ vh, const __nv_bfloat16* __restrict__ vl,
                 const __nv_bfloat16* __restrict__ qp, const __nv_bfloat16* __restrict__ kp,
                 __nv_bfloat16* __restrict__ ch, __nv_bfloat16* __restrict__ cl)
{
    extern __shared__ char smraw[];
    uint32_t sb = smem_u32(smraw);
    int tid = threadIdx.x;
    int l = tid & 31, w = tid >> 5;
    int bid = blockIdx.x;
    int qt = bid & 15;
    int h  = (bid >> 4) & 7;
    int b  = bid >> 7;
    int l0 = qt << 6;

    {
#pragma unroll
        for (int i = 0; i < 8; i++) {
            int id = i * 128 + tid;
            int row = id >> 4, c = id & 15;
            int lq = l0 + row;
            const __nv_bfloat16* base = (c < 8) ? qh : ql;
            const __nv_bfloat16* src = base + ((size_t)(b * LSEQ + (lq < LSEQ ? lq : 0))) * DM + h * DKH + (c & 7) * 8;
            cpa16z(SWZ(sb + SQ_OFF, row, c), src, lq < LSEQ ? 16 : 0);
        }
        int row = tid >> 1, cc = tid & 1;
        int lq = l0 + row;
        const __nv_bfloat16* src = qp + ((size_t)((b * LSEQ + (lq < LSEQ ? lq : 0)) * NH + h)) * PP + cc * 8;
        cpa16z(sb + SQP_OFF + row * 48 + cc * 16, src, lq < LSEQ ? 16 : 0);
    }

#define A_LOAD_STAGE(st, buf) do { \
    uint32_t so = sb + STG_OFF + (buf) * STG_SZ; \
    _Pragma("unroll") \
    for (int i = 0; i < 8; i++) { \
        int id = i * 128 + tid; \
        int row = id >> 4, c = id & 15; \
        int s = (st) * 64 + row; \
        int ok = (s < LSEQ) ? 16 : 0; \
        size_t go = ((size_t)(b * LSEQ + (s < LSEQ ? s : 0))) * DM + h * DKH + (c & 7) * 8; \
        cpa16z(SWZ(so, row, c),         ((c < 8) ? kh : kl) + go, ok); \
        cpa16z(SWZ(so + 16384, row, c), ((c < 8) ? vh : vl) + go, ok); \
    } \
    { \
        int row = tid >> 1, cc = tid & 1; \
        int s = (st) * 64 + row; \
        const __nv_bfloat16* src = kp + ((size_t)((b * LSEQ + (s < LSEQ ? s : 0)) * NH + h)) * PP + cc * 8; \
        cpa16z(so + 32768 + row * 48 + cc * 16, src, s < LSEQ ? 16 : 0); \
    } \
} while (0)

    A_LOAD_STAGE(0, 0);
    CP_COMMIT();

    float o[8][4];
#pragma unroll
    for (int i = 0; i < 8; i++)
#pragma unroll
        for (int j = 0; j < 4; j++) o[i][j] = 0.f;
    float m0 = -1e30f, m1 = -1e30f, L0 = 0.f, L1 = 0.f;

    uint32_t aqh[4][4], aql[4][4], aqp[4];

    for (int st = 0; st < 16; st++) {
        int p = st & 1;
        if (st + 1 < 16) {
            A_LOAD_STAGE(st + 1, p ^ 1);
            CP_COMMIT();
            CP_WAIT(1);
        } else {
            CP_WAIT(0);
        }
        __syncthreads();

        if (st == 0) {
#pragma unroll
            for (int kt = 0; kt < 4; kt++) {
                int ra = w * 16 + (l & 15);
                int ca = kt * 2 + ((l >> 4) & 1);
                ldsm4(aqh[kt], SWZ(sb + SQ_OFF, ra, ca));
                ldsm4(aql[kt], SWZ(sb + SQ_OFF, ra, ca + 8));
            }
            ldsm4(aqp, sb + SQP_OFF + (w * 16 + (l & 15)) * 48 + ((l >> 4) & 1) * 16);
        }

        uint32_t so = sb + STG_OFF + p * STG_SZ;

        float msk[8][4];
#pragma unroll
        for (int i = 0; i < 8; i++)
#pragma unroll
            for (int j = 0; j < 4; j++) msk[i][j] = 0.f;
#pragma unroll
        for (int g = 0; g < 4; g++) {
            int rk = g * 16 + (l & 7) + ((l >> 4) & 1) * 8;
            uint32_t bkp[4];
            ldsm4(bkp, so + 32768 + rk * 48 + ((l >> 3) & 1) * 16);
            mma16816(msk[g * 2 + 0], aqp, bkp);
            mma16816(msk[g * 2 + 1], aqp, bkp + 2);
        }

        float sc[8][4];
#pragma unroll
        for (int i = 0; i < 8; i++)
#pragma unroll
            for (int j = 0; j < 4; j++) sc[i][j] = 0.f;
#pragma unroll
        for (int kt = 0; kt < 4; kt++) {
#pragma unroll
            for (int g = 0; g < 4; g++) {
                int rk = g * 16 + (l & 7) + ((l >> 4) & 1) * 8;
                int ck = kt * 2 + ((l >> 3) & 1);
                uint32_t bh[4], bl_[4];
                ldsm4(bh,  SWZ(so, rk, ck));
                ldsm4(bl_, SWZ(so, rk, ck + 8));
                mma16816(sc[g * 2 + 0], aqh[kt], bh);
                mma16816(sc[g * 2 + 1], aqh[kt], bh + 2);
                mma16816(sc[g * 2 + 0], aql[kt], bh);
                mma16816(sc[g * 2 + 1], aql[kt], bh + 2);
                mma16816(sc[g * 2 + 0], aqh[kt], bl_);
                mma16816(sc[g * 2 + 1], aqh[kt], bl_ + 2);
            }
        }

        int s0 = st << 6;
#pragma unroll
        for (int nt = 0; nt < 8; nt++) {
#pragma unroll
            for (int j = 0; j < 4; j++) {
                int col = nt * 8 + (l & 3) * 2 + (j & 1);
                float s = sc[nt][j] * 0.125f + tanh_fast(msk[nt][j]);
                sc[nt][j] = (s0 + col < LSEQ) ? s : -1e30f;
            }
        }

        float mx0 = -1e30f, mx1 = -1e30f;
#pragma unroll
        for (int nt = 0; nt < 8; nt++) {
            mx0 = fmaxf(mx0, fmaxf(sc[nt][0], sc[nt][1]));
            mx1 = fmaxf(mx1, fmaxf(sc[nt][2], sc[nt][3]));
        }
        mx0 = fmaxf(mx0, __shfl_xor_sync(0xffffffffu, mx0, 1));
        mx0 = fmaxf(mx0, __shfl_xor_sync(0xffffffffu, mx0, 2));
        mx1 = fmaxf(mx1, __shfl_xor_sync(0xffffffffu, mx1, 1));
        mx1 = fmaxf(mx1, __shfl_xor_sync(0xffffffffu, mx1, 2));
        float m0n = fmaxf(m0, mx0), m1n = fmaxf(m1, mx1);
        float f0 = __expf(m0 - m0n), f1 = __expf(m1 - m1n);
        m0 = m0n; m1 = m1n;
        float sum0 = 0.f, sum1 = 0.f;
#pragma unroll
        for (int nt = 0; nt < 8; nt++) {
            float p0 = __expf(sc[nt][0] - m0n), p1 = __expf(sc[nt][1] - m0n);
            float p2 = __expf(sc[nt][2] - m1n), p3 = __expf(sc[nt][3] - m1n);
            sc[nt][0] = p0; sc[nt][1] = p1; sc[nt][2] = p2; sc[nt][3] = p3;
            sum0 += p0 + p1; sum1 += p2 + p3;
        }
        sum0 += __shfl_xor_sync(0xffffffffu, sum0, 1);
        sum0 += __shfl_xor_sync(0xffffffffu, sum0, 2);
        sum1 += __shfl_xor_sync(0xffffffffu, sum1, 1);
        sum1 += __shfl_xor_sync(0xffffffffu, sum1, 2);
        L0 = L0 * f0 + sum0;
        L1 = L1 * f1 + sum1;
#pragma unroll
        for (int nt = 0; nt < 8; nt++) {
            o[nt][0] *= f0; o[nt][1] *= f0;
            o[nt][2] *= f1; o[nt][3] *= f1;
        }

#pragma unroll
        for (int kt = 0; kt < 4; kt++) {
            uint32_t ph[4], pl[4];
            ph[0] = pack_hi(sc[2 * kt][0],     sc[2 * kt][1]);
            ph[1] = pack_hi(sc[2 * kt][2],     sc[2 * kt][3]);
            ph[2] = pack_hi(sc[2 * kt + 1][0], sc[2 * kt + 1][1]);
            ph[3] = pack_hi(sc[2 * kt + 1][2], sc[2 * kt + 1][3]);
            pl[0] = pack_lo(sc[2 * kt][0],     sc[2 * kt][1]);
            pl[1] = pack_lo(sc[2 * kt][2],     sc[2 * kt][3]);
            pl[2] = pack_lo(sc[2 * kt + 1][0], sc[2 * kt + 1][1]);
            pl[3] = pack_lo(sc[2 * kt + 1][2], sc[2 * kt + 1][3]);
#pragma unroll
            for (int dp = 0; dp < 4; dp++) {
                int rv = kt * 16 + (l & 7) + ((l >> 3) & 1) * 8;
                int cv = dp * 2 + ((l >> 4) & 1);
                uint32_t bvh[4], bvl[4];
                ldsm4t(bvh, SWZ(so + 16384, rv, cv));
                ldsm4t(bvl, SWZ(so + 16384, rv, cv + 8));
                mma16816(o[dp * 2 + 0], ph, bvh);
                mma16816(o[dp * 2 + 1], ph, bvh + 2);
                mma16816(o[dp * 2 + 0], pl, bvh);
                mma16816(o[dp * 2 + 1], pl, bvh + 2);
                mma16816(o[dp * 2 + 0], ph, bvl);
                mma16816(o[dp * 2 + 1], ph, bvl + 2);
            }
        }
        __syncthreads();
    }

    float rs0 = 1.f / L0, rs1 = 1.f / L1;
    int r0 = w * 16 + (l >> 2);
    int lq0 = l0 + r0, lq1 = lq0 + 8;
#pragma unroll
    for (int dt = 0; dt < 8; dt++) {
        int col = h * DKH + dt * 8 + (l & 3) * 2;
        if (lq0 < LSEQ) {
            size_t off = (size_t)(b * LSEQ + lq0) * DM + col;
            float v0 = o[dt][0] * rs0, v1 = o[dt][1] * rs0;
            *(uint32_t*)&ch[off] = pack_hi(v0, v1);
            *(uint32_t*)&cl[off] = pack_lo(v0, v1);
        }
        if (lq1 < LSEQ) {
            size_t off = (size_t)(b * LSEQ + lq1) * DM + col;
            float v2 = o[dt][2] * rs1, v3 = o[dt][3] * rs1;
            *(uint32_t*)&ch[off] = pack_hi(v2, v3);
            *(uint32_t*)&cl[off] = pack_lo(v2, v3);
        }
    }
}

// ---------------- LayerNorm (+ optional split out) ----------------
__global__ __launch_bounds__(128)
void ln_kernel(float* __restrict__ out, const float* __restrict__ a,
               const float* __restrict__ y, const float* __restrict__ g,
               const float* __restrict__ bb,
               __nv_bfloat16* __restrict__ oh, __nv_bfloat16* __restrict__ ol)
{
    int row = blockIdx.x, tid = threadIdx.x;
    float4 v = ((const float4*)(a + (long)row * DM))[tid];
    if (y) {
        float4 vy = ((const float4*)(y + (long)row * DM))[tid];
        v.x += vy.x; v.y += vy.y; v.z += vy.z; v.w += vy.w;
    }
    float s  = v.x + v.y + v.z + v.w;
    float sq = v.x * v.x + v.y * v.y + v.z * v.z + v.w * v.w;
#pragma unroll
    for (int o = 16; o > 0; o >>= 1) {
        s  += __shfl_xor_sync(0xffffffffu, s,  o);
        sq += __shfl_xor_sync(0xffffffffu, sq, o);
    }
    __shared__ float shs[4], shq[4];
    int wid = tid >> 5;
    if ((tid & 31) == 0) { shs[wid] = s; shq[wid] = sq; }
    __syncthreads();
    s  = shs[0] + shs[1] + shs[2] + shs[3];
    sq = shq[0] + shq[1] + shq[2] + shq[3];
    float mean = s * (1.f / DM);
    float var  = sq * (1.f / DM) - mean * mean;
    float rstd = rsqrtf(var + 1e-5f);
    float4 gg = ((const float4*)g)[tid];
    float4 bv = ((const float4*)bb)[tid];
    float4 o4;
    o4.x = (v.x - mean) * rstd * gg.x + bv.x;
    o4.y = (v.y - mean) * rstd * gg.y + bv.y;
    o4.z = (v.z - mean) * rstd * gg.z + bv.z;
    o4.w = (v.w - mean) * rstd * gg.w + bv.w;
    ((float4*)(out + (long)row * DM))[tid] = o4;
    if (oh) {
        ((uint32_t*)(oh + (long)row * DM))[tid * 2]     = pack_hi(o4.x, o4.y);
        ((uint32_t*)(oh + (long)row * DM))[tid * 2 + 1] = pack_hi(o4.z, o4.w);
        ((uint32_t*)(ol + (long)row * DM))[tid * 2]     = pack_lo(o4.x, o4.y);
        ((uint32_t*)(ol + (long)row * DM))[tid * 2 + 1] = pack_lo(o4.z, o4.w);
    }
}

// ---------------- fused double-norm: h = LN(LN(h+y)+y), split out ----------------
__global__ __launch_bounds__(128)
void ln2x_kernel(float* __restrict__ hout, const float* __restrict__ hin,
                 const float* __restrict__ y, const float* __restrict__ g,
                 const float* __restrict__ bb,
                 __nv_bfloat16* __restrict__ oh, __nv_bfloat16* __restrict__ ol)
{
    int row = blockIdx.x, tid = threadIdx.x;
    int wid = tid >> 5;
    __shared__ float shs[4], shq[4];

    float4 vy = ((const float4*)(y + (long)row * DM))[tid];
    float4 v  = ((const float4*)(hin + (long)row * DM))[tid];
    v.x += vy.x; v.y += vy.y; v.z += vy.z; v.w += vy.w;
    float4 gg = ((const float4*)g)[tid];
    float4 bv = ((const float4*)bb)[tid];

#pragma unroll
    for (int pass = 0; pass < 2; pass++) {
        float s  = v.x + v.y + v.z + v.w;
        float sq = v.x * v.x + v.y * v.y + v.z * v.z + v.w * v.w;
#pragma unroll
        for (int o = 16; o > 0; o >>= 1) {
            s  += __shfl_xor_sync(0xffffffffu, s,  o);
            sq += __shfl_xor_sync(0xffffffffu, sq, o);
        }
        if ((tid & 31) == 0) { shs[wid] = s; shq[wid] = sq; }
        __syncthreads();
        s  = shs[0] + shs[1] + shs[2] + shs[3];
        sq = shq[0] + shq[1] + shq[2] + shq[3];
        __syncthreads();
        float mean = s * (1.f / DM);
        float var  = sq * (1.f / DM) - mean * mean;
        float rstd = rsqrtf(var + 1e-5f);
        v.x = (v.x - mean) * rstd * gg.x + bv.x;
        v.y = (v.y - mean) * rstd * gg.y + bv.y;
        v.z = (v.z - mean) * rstd * gg.z + bv.z;
        v.w = (v.w - mean) * rstd * gg.w + bv.w;
        if (pass == 0) { v.x += vy.x; v.y += vy.y; v.z += vy.z; v.w += vy.w; }
    }

    ((float4*)(hout + (long)row * DM))[tid] = v;
    ((uint32_t*)(oh + (long)row * DM))[tid * 2]     = pack_hi(v.x, v.y);
    ((uint32_t*)(oh + (long)row * DM))[tid * 2 + 1] = pack_hi(v.z, v.w);
    ((uint32_t*)(ol + (long)row * DM))[tid * 2]     = pack_lo(v.x, v.y);
    ((uint32_t*)(ol + (long)row * DM))[tid * 2 + 1] = pack_lo(v.z, v.w);
}

// ---------------- final FC on last token ----------------
__global__ __launch_bounds__(64)
void fc_kernel(const float* __restrict__ hin, const float* __restrict__ w,
               const float* __restrict__ b, float* __restrict__ out)
{
    __shared__ float sh[512];
    int tid = threadIdx.x;
    int bb  = blockIdx.x;
    const float* row = hin + ((long)bb * LSEQ + (LSEQ - 1)) * DM;
    for (int i = tid; i < 512; i += 64) sh[i] = row[i];
    __syncthreads();
    if (tid < 50) {
        float a = b[tid];
#pragma unroll 8
        for (int d = 0; d < 512; d++) a += sh[d] * w[d * 50 + tid];
        out[bb * 50 + tid] = a;
    }
}

// ---------------- launch ----------------
extern "C" void kernel_launch(void* const* d_in, const int* in_sizes, int n_in,
                              void* d_out, int out_size)
{
    const float* x     = (const float*)d_in[0];
    const float* emb_w = (const float*)d_in[1];
    const float* emb_b = (const float*)d_in[2];
    const float* pe    = (const float*)d_in[3];
    const float* Wq    = (const float*)d_in[4];
    const float* bq    = (const float*)d_in[5];
    const float* Wk    = (const float*)d_in[6];
    const float* bk    = (const float*)d_in[7];
    const float* Wv    = (const float*)d_in[8];
    const float* bv    = (const float*)d_in[9];
    const float* Wo    = (const float*)d_in[10];
    const float* bo    = (const float*)d_in[11];
    const float* W1    = (const float*)d_in[12];
    const float* b1    = (const float*)d_in[13];
    const float* W2    = (const float*)d_in[14];
    const float* b2    = (const float*)d_in[15];
    const float* g1    = (const float*)d_in[16];
    const float* be1   = (const float*)d_in[17];
    const float* g2    = (const float*)d_in[18];
    const float* be2   = (const float*)d_in[19];
    const float* lm_qw = (const float*)d_in[20];
    const float* lm_qb = (const float*)d_in[21];
    const float* lm_kw = (const float*)d_in[22];
    const float* lm_kb = (const float*)d_in[23];
    const float* gn    = (const float*)d_in[24];
    const float* bn    = (const float*)d_in[25];
    const float* fc_w  = (const float*)d_in[26];
    const float* fc_b  = (const float*)d_in[27];
    float* out = (float*)d_out;

    float *h, *t1, *t2;
    cudaGetSymbolAddress((void**)&h,  g_h);
    cudaGetSymbolAddress((void**)&t1, g_t1);
    cudaGetSymbolAddress((void**)&t2, g_t2);

    __nv_bfloat16 *wqh, *wql, *wkh, *wkl, *wvh, *wvl, *woh, *wol;
    __nv_bfloat16 *w1h, *w1l, *w2h, *w2l, *ah, *al, *ffh, *ffl;
    __nv_bfloat16 *qh, *ql, *kh, *kl, *vh, *vl, *qpb, *kpb;
    cudaGetSymbolAddress((void**)&wqh, g_wqh);
    cudaGetSymbolAddress((void**)&wql, g_wql);
    cudaGetSymbolAddress((void**)&wkh, g_wkh);
    cudaGetSymbolAddress((void**)&wkl, g_wkl);
    cudaGetSymbolAddress((void**)&wvh, g_wvh);
    cudaGetSymbolAddress((void**)&wvl, g_wvl);
    cudaGetSymbolAddress((void**)&woh, g_woh);
    cudaGetSymbolAddress((void**)&wol, g_wol);
    cudaGetSymbolAddress((void**)&w1h, g_w1h);
    cudaGetSymbolAddress((void**)&w1l, g_w1l);
    cudaGetSymbolAddress((void**)&w2h, g_w2h);
    cudaGetSymbolAddress((void**)&w2l, g_w2l);
    cudaGetSymbolAddress((void**)&ah,  g_ah);
    cudaGetSymbolAddress((void**)&al,  g_al);
    cudaGetSymbolAddress((void**)&ffh, g_ffh);
    cudaGetSymbolAddress((void**)&ffl, g_ffl);
    cudaGetSymbolAddress((void**)&qh,  g_qh);
    cudaGetSymbolAddress((void**)&ql,  g_ql);
    cudaGetSymbolAddress((void**)&kh,  g_kh);
    cudaGetSymbolAddress((void**)&kl,  g_kl);
    cudaGetSymbolAddress((void**)&vh,  g_vh);
    cudaGetSymbolAddress((void**)&vl,  g_vl);
    cudaGetSymbolAddress((void**)&qpb, g_qp);
    cudaGetSymbolAddress((void**)&kpb, g_kp);

    cudaFuncSetAttribute(attn_kernel, cudaFuncAttributeMaxDynamicSharedMemorySize, ATT_SMEM);
    cudaFuncSetAttribute(mma_gemm,    cudaFuncAttributeMaxDynamicSharedMemorySize, MMA_SMEM);
    cudaFuncSetAttribute(qkv_gemm,    cudaFuncAttributeMaxDynamicSharedMemorySize, MMA_SMEM);

    wsplit_all<<<NL * 3072, 256>>>(Wq, Wk, Wv, Wo, W1, W2,
                                   wqh, wql, wkh, wkl, wvh, wvl, woh, wol,
                                   w1h, w1l, w2h, w2l);
    embed_kernel<<<BL, 128>>>(x, emb_w, emb_b, pe, h, ah, al);

    const int MT = MPAD / 128;     // 63
    dim3 gqkv(DM / 128, MT, 3);
    dim3 gq(DM / 128, MT);
    dim3 gf1(DFF / 128, MT);
    dim3 glm(BL, 2);               // fused q/k lmproj

    for (int i = 0; i < NL; i++) {
        long o512 = (long)i * DM * DM;
        long offf = (long)i * DM * DFF;

        // launch idx (layer 0): 2=qkv, 3=lmproj2, 4=attn, 5=Wo gemm (ncu -s5 -c1 -> Wo)
        qkv_gemm<<<gqkv, 256, MMA_SMEM>>>(ah, al,
                                          wqh + o512, wql + o512, wkh + o512, wkl + o512,
                                          wvh + o512, wvl + o512,
                                          bq + i * DM, bk + i * DM, bv + i * DM,
                                          qh, ql, kh, kl, vh, vl);
        lmproj2_kernel<<<glm, 128>>>(qh, kh, lm_qw, lm_qb, lm_kw, lm_kb, qpb, kpb);

        attn_kernel<<<NB * NH * 16, 128, ATT_SMEM>>>(qh, ql, kh, kl, vh, vl, qpb, kpb, ah, al);

        mma_gemm<<<gq, 256, MMA_SMEM>>>(ah, al, woh + o512, wol + o512, bo + i * DM, t1,
                                        (__nv_bfloat16*)0, (__nv_bfloat16*)0, DM, DM, 2);
        ln_kernel<<<BL, 128>>>(h, h, t1, g1 + i * DM, be1 + i * DM, ah, al);

        mma_gemm<<<gf1, 256, MMA_SMEM>>>(ah, al, w1h + offf, w1l + offf, b1 + i * DFF,
                                         (float*)0, ffh, ffl, DFF, DM, 5);
        mma_gemm<<<gq, 256, MMA_SMEM>>>(ffh, ffl, w2h + offf, w2l + offf, b2 + i * DM, t2,
                                        (__nv_bfloat16*)0, (__nv_bfloat16*)0, DM, DFF, 2);

        ln2x_kernel<<<BL, 128>>>(h, h, t2, g2 + i * DM, be2 + i * DM, ah, al);
    }

    ln_kernel<<<BL, 128>>>(t1, h, (const float*)nullptr, gn, bn,
                           (__nv_bfloat16*)0, (__nv_bfloat16*)0);
    fc_kernel<<<NB, 64>>>(t1, fc_w, fc_b, out);
}